// round 6
// baseline (speedup 1.0000x reference)
#include <cuda_runtime.h>
#include <mma.h>
#include <math.h>

using namespace nvcuda;

// ---------------------------------------------------------------------------
// B=256, RANK=512, R4=128, R2=256
// convT16 GEMM: Z[(b*16+s2)][(co*16+k)] = X2[(b*16+s2)][ci] @ W2[ci][(co*16+k)]
//               M=4096 N=4096 K=128, fold s2+k=t in-block.
// convT2  GEMM: Z[(b*32+t)][(co*2+k)]  = X3[(b*32+t)][ci] @ W3[ci][(co*2+k)]
//               M=8192 N=1024 K=256, fold y[t]=Z[t][2co]+Z[t-1][2co+1], tanh.
// Both tf32x3 (hi*hi + hi*lo + lo*hi), error ~2^-20.
// ---------------------------------------------------------------------------

__device__ float g_latent[256 * 256];           // [ch][b]
__device__ float g_c[256 * 512 * 3];            // [b][r][3]
__device__ float g_xhi[2][4096 * 128];          // [s][(b,s2)][ci]
__device__ float g_xlo[2][4096 * 128];
__device__ float g_w2hi[2][128 * 4096];         // [s][ci][(co,k)]
__device__ float g_w2lo[2][128 * 4096];
__device__ float g_w3hi[2][256 * 1024];         // [s][ci][(co,k)]
__device__ float g_w3lo[2][256 * 1024];
__device__ float g_y2[2 * 256 * 256 * 32];      // [s][b][co][32], t=31 pad 0
__device__ float g_x3hi[2][8192 * 256];         // [s][(b,t)][ci], row t=31 zero
__device__ float g_x3lo[2][8192 * 256];
__device__ float g_psum[2 * 256 * 256];
__device__ float g_psq [2 * 256 * 256];
__device__ float g_sc[2 * 256];
__device__ float g_sh[2 * 256];
__device__ float g_o3[2 * 256 * 512 * 32];      // [s][b][r][32]

__device__ __forceinline__ float tf32hi(float x) {
    return __uint_as_float(__float_as_uint(x) & 0xFFFFE000u);
}

constexpr int SA_LD = 40;                        // 128 x 32 chunk, padded
constexpr int SB_LD = 136;                       // 32 x 128 chunk, padded
constexpr int Z_LD  = 132;                       // 128 x 128 result tile
constexpr int SA_SZ = 128 * SA_LD;
constexpr int SB_SZ = 32 * SB_LD;
constexpr int SM_MAIN_B  = (2 * SA_SZ + 2 * SB_SZ) * 4;          // 75776 B
constexpr int SM_GEMM2_B = (128 * Z_LD + 256 * 36) * 4;          // 104448 B

__device__ __forceinline__ void reduce2_256(float& s, float& ss) {
    __shared__ float rs[8], rss[8];
    #pragma unroll
    for (int o = 16; o > 0; o >>= 1) {
        s  += __shfl_down_sync(0xffffffffu, s,  o);
        ss += __shfl_down_sync(0xffffffffu, ss, o);
    }
    int wid = threadIdx.x >> 5, lane = threadIdx.x & 31;
    if (lane == 0) { rs[wid] = s; rss[wid] = ss; }
    __syncthreads();
    if (threadIdx.x < 32) {
        float a = lane < 8 ? rs[lane] : 0.f;
        float b = lane < 8 ? rss[lane] : 0.f;
        #pragma unroll
        for (int o = 4; o > 0; o >>= 1) {
            a += __shfl_down_sync(0xffffffffu, a, o);
            b += __shfl_down_sync(0xffffffffu, b, o);
        }
        if (lane == 0) { rs[0] = a; rss[0] = b; }
    }
    __syncthreads();
    s = rs[0]; ss = rss[0];
}

// ---------------------------------------------------------------------------
// smem-staged tf32x3 128x128 GEMM tile; result left in sm[128][Z_LD].
// ---------------------------------------------------------------------------
template<int KTOT>
__device__ __forceinline__ void gemm_tf32x3(
    const float* __restrict__ Ahi, const float* __restrict__ Alo,
    const float* __restrict__ Bhi, const float* __restrict__ Blo,
    int m0, int n0, int ldb, float* sm)
{
    int tid = threadIdx.x, w = tid >> 5;
    float* sAh = sm;
    float* sAl = sm + SA_SZ;
    float* sBh = sm + 2 * SA_SZ;
    float* sBl = sBh + SB_SZ;

    wmma::fragment<wmma::accumulator, 16, 16, 8, float> c[8];
    #pragma unroll
    for (int j = 0; j < 8; j++) wmma::fill_fragment(c[j], 0.f);

    int am = tid >> 3, ak = (tid & 7) * 4;
    int bk = tid >> 5, bn = (tid & 31) * 4;

    for (int kc = 0; kc < KTOT; kc += 32) {
        __syncthreads();
        #pragma unroll
        for (int i = 0; i < 4; i++) {
            int m = am + 32 * i;
            *(float4*)(sAh + m * SA_LD + ak) =
                *(const float4*)(Ahi + (size_t)(m0 + m) * KTOT + kc + ak);
            *(float4*)(sAl + m * SA_LD + ak) =
                *(const float4*)(Alo + (size_t)(m0 + m) * KTOT + kc + ak);
        }
        #pragma unroll
        for (int i = 0; i < 4; i++) {
            int k = bk + 8 * i;
            *(float4*)(sBh + k * SB_LD + bn) =
                *(const float4*)(Bhi + (size_t)(kc + k) * ldb + n0 + bn);
            *(float4*)(sBl + k * SB_LD + bn) =
                *(const float4*)(Blo + (size_t)(kc + k) * ldb + n0 + bn);
        }
        __syncthreads();
        #pragma unroll
        for (int k0 = 0; k0 < 32; k0 += 8) {
            wmma::fragment<wmma::matrix_a, 16, 16, 8, wmma::precision::tf32, wmma::row_major> ah, al;
            wmma::load_matrix_sync(ah, sAh + (w * 16) * SA_LD + k0, SA_LD);
            wmma::load_matrix_sync(al, sAl + (w * 16) * SA_LD + k0, SA_LD);
            #pragma unroll
            for (int j = 0; j < 8; j++) {
                wmma::fragment<wmma::matrix_b, 16, 16, 8, wmma::precision::tf32, wmma::row_major> bh, bl;
                wmma::load_matrix_sync(bh, sBh + k0 * SB_LD + j * 16, SB_LD);
                wmma::load_matrix_sync(bl, sBl + k0 * SB_LD + j * 16, SB_LD);
                wmma::mma_sync(c[j], ah, bh, c[j]);
                wmma::mma_sync(c[j], ah, bl, c[j]);
                wmma::mma_sync(c[j], al, bh, c[j]);
            }
        }
    }
    __syncthreads();
    #pragma unroll
    for (int j = 0; j < 8; j++)
        wmma::store_matrix_sync(sm + (w * 16) * Z_LD + j * 16, c[j], Z_LD, wmma::mem_row_major);
    __syncthreads();
}

// ---------------------------------------------------------------------------
// Stage 1: latent = [lrelu(BN(noise@W.T+b),0.01) ; emb[label]], channel-major.
// ---------------------------------------------------------------------------
__global__ void k_latent(const float* __restrict__ noise, const int* __restrict__ label,
                         const float* __restrict__ lin_w, const float* __restrict__ lin_b,
                         const float* __restrict__ g,     const float* __restrict__ be,
                         const float* __restrict__ emb) {
    int j = blockIdx.x, b = threadIdx.x;
    if (j >= 128) {
        int jj = j - 128;
        g_latent[(128 + jj) * 256 + b] = emb[label[b] * 128 + jj];
        return;
    }
    __shared__ float wsm[100];
    if (b < 100) wsm[b] = lin_w[j * 100 + b];
    __syncthreads();
    float acc = lin_b[j];
    const float* nb = noise + b * 100;
    #pragma unroll 4
    for (int i = 0; i < 100; i++) acc += nb[i] * wsm[i];
    float s = acc, ss = acc * acc;
    reduce2_256(s, ss);
    float mean = s * (1.f / 256.f);
    float var  = ss * (1.f / 256.f) - mean * mean;
    float sc   = g[j] * rsqrtf(var + 1e-5f);
    float v    = (acc - mean) * sc + be[j];
    g_latent[j * 256 + b] = v >= 0.f ? v : 0.01f * v;
}

// ---------------------------------------------------------------------------
// Weight splits into tf32 hi/lo (already row-major for the GEMMs).
// ---------------------------------------------------------------------------
__global__ void k_wsplit2(const float* __restrict__ hW2, const float* __restrict__ wW2) {
    int s_ = blockIdx.y;
    int i = blockIdx.x * 256 + threadIdx.x;
    float x = (s_ ? wW2 : hW2)[i];
    float h = tf32hi(x);
    g_w2hi[s_][i] = h;
    g_w2lo[s_][i] = tf32hi(x - h);
}
__global__ void k_wsplit3(const float* __restrict__ hW3, const float* __restrict__ wW3) {
    int s_ = blockIdx.y;
    int i = blockIdx.x * 256 + threadIdx.x;
    float x = (s_ ? wW3 : hW3)[i];
    float h = tf32hi(x);
    g_w3hi[s_][i] = h;
    g_w3lo[s_][i] = tf32hi(x - h);
}

// ---------------------------------------------------------------------------
// Stage 2 merged: blocks [0,512) = c-branch; [512,768) = h/w conv1.
// h/w branch writes X2 GEMM layout [(b*16+s2)][ci], split hi/lo.
// ---------------------------------------------------------------------------
__global__ void __launch_bounds__(256)
k_conv1(const float* __restrict__ cW, const float* __restrict__ cB,
        const float* __restrict__ cG, const float* __restrict__ cBe,
        const float* __restrict__ hW, const float* __restrict__ hB,
        const float* __restrict__ hG, const float* __restrict__ hBe,
        const float* __restrict__ wW, const float* __restrict__ wB,
        const float* __restrict__ wG, const float* __restrict__ wBe) {
    int b = threadIdx.x;
    if (blockIdx.x < 512) {
        int co = blockIdx.x;
        __shared__ float ws[256 * 3];
        for (int i = b; i < 256 * 3; i += 256)
            ws[i] = cW[(i / 3) * 512 * 3 + co * 3 + (i % 3)];
        __syncthreads();
        float bv = cB[co];
        float a0 = bv, a1 = bv, a2 = bv;
        for (int ci = 0; ci < 256; ci++) {
            float x = g_latent[ci * 256 + b];
            a0 += x * ws[ci * 3 + 0];
            a1 += x * ws[ci * 3 + 1];
            a2 += x * ws[ci * 3 + 2];
        }
        float s = a0 + a1 + a2, ss = a0 * a0 + a1 * a1 + a2 * a2;
        reduce2_256(s, ss);
        const float invN = 1.f / 768.f;
        float mean = s * invN, var = ss * invN - mean * mean;
        float sc = cG[co] * rsqrtf(var + 1e-5f);
        float sh = cBe[co] - mean * sc;
        float v0 = a0 * sc + sh, v1 = a1 * sc + sh, v2 = a2 * sc + sh;
        float* o = g_c + (b * 512 + co) * 3;
        o[0] = v0 >= 0.f ? v0 : 0.2f * v0;
        o[1] = v1 >= 0.f ? v1 : 0.2f * v1;
        o[2] = v2 >= 0.f ? v2 : 0.2f * v2;
    } else {
        int bi = blockIdx.x - 512;
        int s_ = bi >> 7, co = bi & 127;
        const float* W  = s_ ? wW  : hW;
        const float* Bi = s_ ? wB  : hB;
        const float* G  = s_ ? wG  : hG;
        const float* Be = s_ ? wBe : hBe;
        __shared__ float ws[256 * 16];
        for (int i = b; i < 256 * 16; i += 256)
            ws[i] = W[(i >> 4) * 128 * 16 + co * 16 + (i & 15)];
        __syncthreads();
        float acc[16];
        float bv = Bi[co];
        #pragma unroll
        for (int t = 0; t < 16; t++) acc[t] = bv;
        for (int ci = 0; ci < 256; ci++) {
            float x = g_latent[ci * 256 + b];
            const float4* w4 = (const float4*)(ws + ci * 16);
            float4 wa = w4[0], wb = w4[1], wc = w4[2], wd = w4[3];
            acc[0] += x * wa.x; acc[1] += x * wa.y; acc[2]  += x * wa.z; acc[3]  += x * wa.w;
            acc[4] += x * wb.x; acc[5] += x * wb.y; acc[6]  += x * wb.z; acc[7]  += x * wb.w;
            acc[8] += x * wc.x; acc[9] += x * wc.y; acc[10] += x * wc.z; acc[11] += x * wc.w;
            acc[12]+= x * wd.x; acc[13]+= x * wd.y; acc[14] += x * wd.z; acc[15] += x * wd.w;
        }
        float s = 0.f, ss = 0.f;
        #pragma unroll
        for (int t = 0; t < 16; t++) { s += acc[t]; ss += acc[t] * acc[t]; }
        reduce2_256(s, ss);
        const float invN = 1.f / (256.f * 16.f);
        float mean = s * invN, var = ss * invN - mean * mean;
        float sc = G[co] * rsqrtf(var + 1e-5f);
        float sh = Be[co] - mean * sc;
        float* xh = g_xhi[s_];
        float* xl = g_xlo[s_];
        #pragma unroll
        for (int t = 0; t < 16; t++) {
            float v = acc[t] * sc + sh;
            v = v >= 0.f ? v : 0.2f * v;
            float h = tf32hi(v);
            int idx = (b * 16 + t) * 128 + co;
            xh[idx] = h;
            xl[idx] = tf32hi(v - h);
        }
    }
}

// ---------------------------------------------------------------------------
// Stage 3: convT16 GEMM (smem-staged) + overlap-add fold + BN partials.
// grid (32, 32, 2), 256 threads.
// ---------------------------------------------------------------------------
__global__ void __launch_bounds__(256)
k_gemm16(const float* __restrict__ hB2, const float* __restrict__ wB2) {
    extern __shared__ float sm[];
    int s_ = blockIdx.z;
    gemm_tf32x3<128>(g_xhi[s_], g_xlo[s_], g_w2hi[s_], g_w2lo[s_],
                     blockIdx.y * 128, blockIdx.x * 128, 4096, sm);

    const float* Bi = s_ ? wB2 : hB2;
    int pair = threadIdx.x >> 2, sub = threadIdx.x & 3;
    int bb = pair >> 3, cc = pair & 7;
    int b  = blockIdx.y * 8 + bb;
    int co = blockIdx.x * 8 + cc;
    float bias = Bi[co];
    float psum = 0.f, psq = 0.f;
    float* yo = g_y2 + s_ * (256 * 256 * 32) + (b * 256 + co) * 32;
    const float* zrow = sm + (bb * 16) * Z_LD + cc * 16;
    #pragma unroll
    for (int ti = 0; ti < 8; ti++) {
        int t = sub + ti * 4;
        float v = 0.f;
        if (t < 31) {
            #pragma unroll
            for (int k = 0; k < 16; k++) {
                int s2 = t - k;
                if (s2 >= 0 && s2 < 16) v += zrow[s2 * Z_LD + k];
            }
            v += bias;
        }
        yo[t] = v;
        psum += v;
        psq  += v * v;
    }
    psum += __shfl_down_sync(0xffffffffu, psum, 2, 4);
    psum += __shfl_down_sync(0xffffffffu, psum, 1, 4);
    psq  += __shfl_down_sync(0xffffffffu, psq, 2, 4);
    psq  += __shfl_down_sync(0xffffffffu, psq, 1, 4);
    if (sub == 0) {
        g_psum[s_ * 65536 + b * 256 + co] = psum;
        g_psq [s_ * 65536 + b * 256 + co] = psq;
    }
}

// ---------------------------------------------------------------------------
// Stage 3b: BN partial reduce -> per-channel scale/shift. grid 16 x 256.
// ---------------------------------------------------------------------------
__global__ void __launch_bounds__(256)
k_bnstat(const float* __restrict__ hG, const float* __restrict__ hBe,
         const float* __restrict__ wG, const float* __restrict__ wBe) {
    int s_  = blockIdx.x >> 3;
    int co0 = (blockIdx.x & 7) * 32;
    int col = threadIdx.x & 31, bp = threadIdx.x >> 5;
    const float* ps = g_psum + s_ * 65536 + co0 + col;
    const float* pq = g_psq  + s_ * 65536 + co0 + col;
    float sum = 0.f, sq = 0.f;
    #pragma unroll 8
    for (int i = 0; i < 32; i++) {
        int b = bp + 8 * i;
        sum += ps[b * 256];
        sq  += pq[b * 256];
    }
    __shared__ float ssum[8][32], ssq[8][32];
    ssum[bp][col] = sum; ssq[bp][col] = sq;
    __syncthreads();
    if (bp == 0) {
        #pragma unroll
        for (int r = 1; r < 8; r++) { sum += ssum[r][col]; sq += ssq[r][col]; }
        const float* G  = s_ ? wG  : hG;
        const float* Be = s_ ? wBe : hBe;
        int co = co0 + col;
        const float invN = 1.f / (256.f * 31.f);
        float mean = sum * invN, var = sq * invN - mean * mean;
        float sc = G[co] * rsqrtf(var + 1e-5f);
        g_sc[s_ * 256 + co] = sc;
        g_sh[s_ * 256 + co] = Be[co] - mean * sc;
    }
}

// ---------------------------------------------------------------------------
// Stage 4a: X3 prep — BN+lrelu on y2, transpose to [(b,t)][ci], hi/lo split.
// grid 512 (s,b); 256 threads = ci.
// ---------------------------------------------------------------------------
__global__ void __launch_bounds__(256)
k_xprep() {
    int s_ = blockIdx.x >> 8, b = blockIdx.x & 255, tid = threadIdx.x;
    __shared__ float scs[256], shs[256];
    __shared__ float Xs[256 * 33];
    scs[tid] = g_sc[s_ * 256 + tid];
    shs[tid] = g_sh[s_ * 256 + tid];
    __syncthreads();
    const float4* in4 = (const float4*)(g_y2 + s_ * (256 * 256 * 32) + b * 8192);
    #pragma unroll
    for (int r = 0; r < 8; r++) {
        int i = tid + 256 * r;
        float4 v = in4[i];
        int ci = i >> 3;
        float sc = scs[ci], sh = shs[ci];
        float x0 = v.x * sc + sh; x0 = x0 >= 0.f ? x0 : 0.2f * x0;
        float x1 = v.y * sc + sh; x1 = x1 >= 0.f ? x1 : 0.2f * x1;
        float x2 = v.z * sc + sh; x2 = x2 >= 0.f ? x2 : 0.2f * x2;
        float x3 = v.w * sc + sh; x3 = x3 >= 0.f ? x3 : 0.2f * x3;
        if ((i & 7) == 7) x3 = 0.f;                      // t==31 pad row
        int base = ci * 33 + (i & 7) * 4;
        Xs[base] = x0; Xs[base + 1] = x1; Xs[base + 2] = x2; Xs[base + 3] = x3;
    }
    __syncthreads();
    float* xh = g_x3hi[s_] + (size_t)b * 32 * 256 + tid;
    float* xl = g_x3lo[s_] + (size_t)b * 32 * 256 + tid;
    #pragma unroll
    for (int t = 0; t < 32; t++) {
        float v = Xs[tid * 33 + t];
        float h = tf32hi(v);
        xh[t * 256] = h;
        xl[t * 256] = tf32hi(v - h);
    }
}

// ---------------------------------------------------------------------------
// Stage 4b: convT2 GEMM (smem-staged) + fold + tanh + coalesced store.
// grid (8, 64, 2), 256 threads.
// ---------------------------------------------------------------------------
__global__ void __launch_bounds__(256)
k_gemm2(const float* __restrict__ hB3, const float* __restrict__ wB3) {
    extern __shared__ float sm[];
    int s_ = blockIdx.z;
    gemm_tf32x3<256>(g_x3hi[s_], g_x3lo[s_], g_w3hi[s_], g_w3lo[s_],
                     blockIdx.y * 128, blockIdx.x * 128, 1024, sm);

    const float* Bi = s_ ? wB3 : hB3;
    int tid = threadIdx.x;
    int bb = tid >> 6, co = tid & 63;
    float bias = Bi[blockIdx.x * 64 + co];
    float y[32];
    const float* zb = sm + (bb * 32) * Z_LD;
    #pragma unroll
    for (int t = 0; t < 32; t++) {
        float z = zb[t * Z_LD + co * 2] + bias;
        if (t > 0) z += zb[(t - 1) * Z_LD + co * 2 + 1];
        y[t] = tanhf(z);
    }
    __syncthreads();
    float* yb = sm + 128 * Z_LD;
    #pragma unroll
    for (int t = 0; t < 32; t++) yb[(bb * 64 + co) * 36 + t] = y[t];
    __syncthreads();
    #pragma unroll
    for (int b2 = 0; b2 < 4; b2++) {
        float* o = g_o3 + s_ * (256 * 512 * 32)
                 + (((blockIdx.y * 4 + b2) * 512) + blockIdx.x * 64) * 32;
        for (int i = tid; i < 2048; i += 256)
            o[i] = yb[(b2 * 64 + (i >> 5)) * 36 + (i & 31)];
    }
}

// ---------------------------------------------------------------------------
// Stage 5: out[b,ch,y,x] = sum_r c[b,r,ch]*coef[r] * h[b,r,y] * w[b,r,x]
// ---------------------------------------------------------------------------
__global__ void k_final(const float* __restrict__ coef, float* __restrict__ out) {
    int b = blockIdx.x, tid = threadIdx.x;
    int y = tid >> 5, x = tid & 31;
    __shared__ float shh[32 * 32], shw[32 * 32], shc[32 * 3];
    float a0 = 0.f, a1 = 0.f, a2 = 0.f;
    int ri = tid >> 5, rp = tid & 31;
    for (int r0 = 0; r0 < 512; r0 += 32) {
        shh[tid] = g_o3[                 (b * 512 + r0 + ri) * 32 + rp];
        shw[tid] = g_o3[256 * 512 * 32 + (b * 512 + r0 + ri) * 32 + rp];
        if (tid < 96) {
            int rr = tid / 3, c3 = tid % 3;
            shc[tid] = g_c[(b * 512 + r0 + rr) * 3 + c3] * coef[r0 + rr];
        }
        __syncthreads();
        #pragma unroll
        for (int i = 0; i < 32; i++) {
            float p = shh[i * 32 + y] * shw[i * 32 + x];
            a0 += shc[i * 3 + 0] * p;
            a1 += shc[i * 3 + 1] * p;
            a2 += shc[i * 3 + 2] * p;
        }
        __syncthreads();
    }
    out[((b * 3 + 0) * 32 + y) * 32 + x] = a0;
    out[((b * 3 + 1) * 32 + y) * 32 + x] = a1;
    out[((b * 3 + 2) * 32 + y) * 32 + x] = a2;
}

// ---------------------------------------------------------------------------
extern "C" void kernel_launch(void* const* d_in, const int* in_sizes, int n_in,
                              void* d_out, int out_size) {
    const float* noise  = (const float*)d_in[0];
    const int*   label  = (const int*)  d_in[1];
    const float* lin_w  = (const float*)d_in[2];
    const float* lin_b  = (const float*)d_in[3];
    const float* bn0_g  = (const float*)d_in[4];
    const float* bn0_b  = (const float*)d_in[5];
    const float* emb    = (const float*)d_in[6];
    const float* c_w1   = (const float*)d_in[7];
    const float* c_b1   = (const float*)d_in[8];
    const float* c_g1   = (const float*)d_in[9];
    const float* c_be1  = (const float*)d_in[10];
    const float* h_w1   = (const float*)d_in[11];
    const float* h_b1   = (const float*)d_in[12];
    const float* h_g1   = (const float*)d_in[13];
    const float* h_be1  = (const float*)d_in[14];
    const float* h_w2   = (const float*)d_in[15];
    const float* h_b2   = (const float*)d_in[16];
    const float* h_g2   = (const float*)d_in[17];
    const float* h_be2  = (const float*)d_in[18];
    const float* h_w3   = (const float*)d_in[19];
    const float* h_b3   = (const float*)d_in[20];
    const float* w_w1   = (const float*)d_in[21];
    const float* w_b1   = (const float*)d_in[22];
    const float* w_g1   = (const float*)d_in[23];
    const float* w_be1  = (const float*)d_in[24];
    const float* w_w2   = (const float*)d_in[25];
    const float* w_b2   = (const float*)d_in[26];
    const float* w_g2   = (const float*)d_in[27];
    const float* w_be2  = (const float*)d_in[28];
    const float* w_w3   = (const float*)d_in[29];
    const float* w_b3   = (const float*)d_in[30];
    const float* coef   = (const float*)d_in[31];
    float* out = (float*)d_out;

    cudaFuncSetAttribute(k_gemm16, cudaFuncAttributeMaxDynamicSharedMemorySize, SM_MAIN_B);
    cudaFuncSetAttribute(k_gemm2,  cudaFuncAttributeMaxDynamicSharedMemorySize, SM_GEMM2_B);

    k_wsplit2<<<dim3(2048, 2), 256>>>(h_w2, w_w2);
    k_wsplit3<<<dim3(1024, 2), 256>>>(h_w3, w_w3);
    k_latent <<<256, 256>>>(noise, label, lin_w, lin_b, bn0_g, bn0_b, emb);
    k_conv1  <<<768, 256>>>(c_w1, c_b1, c_g1, c_be1,
                            h_w1, h_b1, h_g1, h_be1,
                            w_w1, w_b1, w_g1, w_be1);
    k_gemm16 <<<dim3(32, 32, 2), 256, SM_MAIN_B>>>(h_b2, w_b2);
    k_bnstat <<<16,  256>>>(h_g2, h_be2, w_g2, w_be2);
    k_xprep  <<<512, 256>>>();
    k_gemm2  <<<dim3(8, 64, 2), 256, SM_GEMM2_B>>>(h_b3, w_b3);
    k_final  <<<256, 1024>>>(coef, out);
}

// round 7
// speedup vs baseline: 2.1717x; 2.1717x over previous
#include <cuda_runtime.h>
#include <cuda_bf16.h>
#include <mma.h>
#include <math.h>

using namespace nvcuda;
typedef __nv_bfloat16 bf16;

// ---------------------------------------------------------------------------
// B=256, RANK=512, R4=128, R2=256
// convT16 GEMM: Z[(b*16+s2)][(co*16+k)] = X2 @ W2   M=4096 N=4096 K=128
// convT2  GEMM: Z[(b*32+t)][(co*2+k)]  = X3 @ W3   M=8192 N=1024 K=256
// Both bf16x3 (hi*hi + hi*lo + lo*hi, fp32 accumulate), err ~2^-18.
// ---------------------------------------------------------------------------

__device__ float g_latent[256 * 256];            // [ch][b]
__device__ float g_c[256 * 512 * 3];             // [b][r][3]
__device__ __align__(16) bf16 g_x2hi[2][4096 * 128];
__device__ __align__(16) bf16 g_x2lo[2][4096 * 128];
__device__ __align__(16) bf16 g_w2hi[2][128 * 4096];
__device__ __align__(16) bf16 g_w2lo[2][128 * 4096];
__device__ __align__(16) bf16 g_w3hi[2][256 * 1024];
__device__ __align__(16) bf16 g_w3lo[2][256 * 1024];
__device__ float g_y2[2 * 256 * 256 * 32];       // raw conv2 out, t=31 pad 0
__device__ __align__(16) bf16 g_x3hi[2][8192 * 256];
__device__ __align__(16) bf16 g_x3lo[2][8192 * 256];
__device__ float g_psum[2 * 256 * 256];
__device__ float g_psq [2 * 256 * 256];
__device__ float g_sc[2 * 256];
__device__ float g_sh[2 * 256];
__device__ float g_o3[2 * 256 * 512 * 32];       // [s][b][r][32]

__device__ __forceinline__ void bf16split(float x, bf16& h, bf16& l) {
    h = __float2bfloat16(x);
    l = __float2bfloat16(x - __bfloat162float(h));
}

constexpr int ALD = 40;     // A chunk row stride (bf16 elems), 128 x 32
constexpr int BLD = 136;    // B chunk row stride, 32 x 128
constexpr int ZLD = 132;    // f32 result tile stride
constexpr int A_ELEMS = 128 * ALD;
constexpr int B_ELEMS = 32 * BLD;
constexpr int SM_LOAD_B  = (2 * A_ELEMS + 2 * B_ELEMS) * 2;      // 37888 B
constexpr int SM_G16_B   = 128 * ZLD * 4;                        // 67584 B
constexpr int SM_G2_B    = 128 * ZLD * 4 + 256 * 36 * 4;         // 104448 B

__device__ __forceinline__ void reduce2_256(float& s, float& ss) {
    __shared__ float rs[8], rss[8];
    #pragma unroll
    for (int o = 16; o > 0; o >>= 1) {
        s  += __shfl_down_sync(0xffffffffu, s,  o);
        ss += __shfl_down_sync(0xffffffffu, ss, o);
    }
    int wid = threadIdx.x >> 5, lane = threadIdx.x & 31;
    if (lane == 0) { rs[wid] = s; rss[wid] = ss; }
    __syncthreads();
    if (threadIdx.x < 32) {
        float a = lane < 8 ? rs[lane] : 0.f;
        float b = lane < 8 ? rss[lane] : 0.f;
        #pragma unroll
        for (int o = 4; o > 0; o >>= 1) {
            a += __shfl_down_sync(0xffffffffu, a, o);
            b += __shfl_down_sync(0xffffffffu, b, o);
        }
        if (lane == 0) { rs[0] = a; rss[0] = b; }
    }
    __syncthreads();
    s = rs[0]; ss = rss[0];
}

// ---------------------------------------------------------------------------
// bf16x3 128x128 block GEMM; 8 warps as 4(m) x 2(n), warp tile 32x64.
// Result stored to Zt (f32, ZLD). Zt may alias the loader buffers.
// ---------------------------------------------------------------------------
template<int KTOT>
__device__ __forceinline__ void gemm_bf16x3(
    const bf16* __restrict__ Ahi, const bf16* __restrict__ Alo,
    const bf16* __restrict__ Bhi, const bf16* __restrict__ Blo,
    int m0, int n0, int ldb, char* smraw, float* Zt)
{
    bf16* sAh = (bf16*)smraw;
    bf16* sAl = sAh + A_ELEMS;
    bf16* sBh = sAl + A_ELEMS;
    bf16* sBl = sBh + B_ELEMS;
    int tid = threadIdx.x, w = tid >> 5;
    int mw = w >> 1, nw = w & 1;

    wmma::fragment<wmma::accumulator, 16, 16, 16, float> c[2][4];
    #pragma unroll
    for (int i = 0; i < 2; i++)
        #pragma unroll
        for (int j = 0; j < 4; j++) wmma::fill_fragment(c[i][j], 0.f);

    for (int kc = 0; kc < KTOT; kc += 32) {
        __syncthreads();
        #pragma unroll
        for (int r = 0; r < 2; r++) {                 // A: 128 rows x 4 segs
            int idx = tid + 256 * r;
            int row = idx >> 2, seg = (idx & 3) * 8;
            *(uint4*)(sAh + row * ALD + seg) =
                *(const uint4*)(Ahi + (size_t)(m0 + row) * KTOT + kc + seg);
            *(uint4*)(sAl + row * ALD + seg) =
                *(const uint4*)(Alo + (size_t)(m0 + row) * KTOT + kc + seg);
        }
        #pragma unroll
        for (int r = 0; r < 2; r++) {                 // B: 32 rows x 16 segs
            int idx = tid + 256 * r;
            int row = idx >> 4, seg = (idx & 15) * 8;
            *(uint4*)(sBh + row * BLD + seg) =
                *(const uint4*)(Bhi + (size_t)(kc + row) * ldb + n0 + seg);
            *(uint4*)(sBl + row * BLD + seg) =
                *(const uint4*)(Blo + (size_t)(kc + row) * ldb + n0 + seg);
        }
        __syncthreads();
        #pragma unroll
        for (int k0 = 0; k0 < 32; k0 += 16) {
            wmma::fragment<wmma::matrix_a, 16, 16, 16, bf16, wmma::row_major> ah[2], al[2];
            #pragma unroll
            for (int i = 0; i < 2; i++) {
                wmma::load_matrix_sync(ah[i], sAh + (mw * 32 + i * 16) * ALD + k0, ALD);
                wmma::load_matrix_sync(al[i], sAl + (mw * 32 + i * 16) * ALD + k0, ALD);
            }
            #pragma unroll
            for (int j = 0; j < 4; j++) {
                wmma::fragment<wmma::matrix_b, 16, 16, 16, bf16, wmma::row_major> bh, bl;
                wmma::load_matrix_sync(bh, sBh + k0 * BLD + nw * 64 + j * 16, BLD);
                wmma::load_matrix_sync(bl, sBl + k0 * BLD + nw * 64 + j * 16, BLD);
                #pragma unroll
                for (int i = 0; i < 2; i++) {
                    wmma::mma_sync(c[i][j], ah[i], bh, c[i][j]);
                    wmma::mma_sync(c[i][j], ah[i], bl, c[i][j]);
                    wmma::mma_sync(c[i][j], al[i], bh, c[i][j]);
                }
            }
        }
    }
    __syncthreads();
    #pragma unroll
    for (int i = 0; i < 2; i++)
        #pragma unroll
        for (int j = 0; j < 4; j++)
            wmma::store_matrix_sync(Zt + (mw * 32 + i * 16) * ZLD + nw * 64 + j * 16,
                                    c[i][j], ZLD, wmma::mem_row_major);
    __syncthreads();
}

// ---------------------------------------------------------------------------
// Stage 1: latent = [lrelu(BN(noise@W.T+b),0.01) ; emb[label]], channel-major.
// ---------------------------------------------------------------------------
__global__ void k_latent(const float* __restrict__ noise, const int* __restrict__ label,
                         const float* __restrict__ lin_w, const float* __restrict__ lin_b,
                         const float* __restrict__ g,     const float* __restrict__ be,
                         const float* __restrict__ emb) {
    int j = blockIdx.x, b = threadIdx.x;
    if (j >= 128) {
        int jj = j - 128;
        g_latent[(128 + jj) * 256 + b] = emb[label[b] * 128 + jj];
        return;
    }
    __shared__ float wsm[100];
    if (b < 100) wsm[b] = lin_w[j * 100 + b];
    __syncthreads();
    float acc = lin_b[j];
    const float* nb = noise + b * 100;
    #pragma unroll 4
    for (int i = 0; i < 100; i++) acc += nb[i] * wsm[i];
    float s = acc, ss = acc * acc;
    reduce2_256(s, ss);
    float mean = s * (1.f / 256.f);
    float var  = ss * (1.f / 256.f) - mean * mean;
    float sc   = g[j] * rsqrtf(var + 1e-5f);
    float v    = (acc - mean) * sc + be[j];
    g_latent[j * 256 + b] = v >= 0.f ? v : 0.01f * v;
}

// ---------------------------------------------------------------------------
// Weight splits (already row-major for the GEMMs).
// ---------------------------------------------------------------------------
__global__ void k_wsplit2(const float* __restrict__ hW2, const float* __restrict__ wW2) {
    int s_ = blockIdx.y;
    int i = blockIdx.x * 256 + threadIdx.x;
    bf16 h, l;
    bf16split((s_ ? wW2 : hW2)[i], h, l);
    g_w2hi[s_][i] = h;
    g_w2lo[s_][i] = l;
}
__global__ void k_wsplit3(const float* __restrict__ hW3, const float* __restrict__ wW3) {
    int s_ = blockIdx.y;
    int i = blockIdx.x * 256 + threadIdx.x;
    bf16 h, l;
    bf16split((s_ ? wW3 : hW3)[i], h, l);
    g_w3hi[s_][i] = h;
    g_w3lo[s_][i] = l;
}

// ---------------------------------------------------------------------------
// Stage 2 merged: blocks [0,512) = c-branch; [512,768) = h/w conv1.
// h/w branch writes X2 GEMM layout [(b*16+s2)][ci] as bf16 hi/lo.
// ---------------------------------------------------------------------------
__global__ void __launch_bounds__(256)
k_conv1(const float* __restrict__ cW, const float* __restrict__ cB,
        const float* __restrict__ cG, const float* __restrict__ cBe,
        const float* __restrict__ hW, const float* __restrict__ hB,
        const float* __restrict__ hG, const float* __restrict__ hBe,
        const float* __restrict__ wW, const float* __restrict__ wB,
        const float* __restrict__ wG, const float* __restrict__ wBe) {
    int b = threadIdx.x;
    if (blockIdx.x < 512) {
        int co = blockIdx.x;
        __shared__ float ws[256 * 3];
        for (int i = b; i < 256 * 3; i += 256)
            ws[i] = cW[(i / 3) * 512 * 3 + co * 3 + (i % 3)];
        __syncthreads();
        float bv = cB[co];
        float a0 = bv, a1 = bv, a2 = bv;
        for (int ci = 0; ci < 256; ci++) {
            float x = g_latent[ci * 256 + b];
            a0 += x * ws[ci * 3 + 0];
            a1 += x * ws[ci * 3 + 1];
            a2 += x * ws[ci * 3 + 2];
        }
        float s = a0 + a1 + a2, ss = a0 * a0 + a1 * a1 + a2 * a2;
        reduce2_256(s, ss);
        const float invN = 1.f / 768.f;
        float mean = s * invN, var = ss * invN - mean * mean;
        float sc = cG[co] * rsqrtf(var + 1e-5f);
        float sh = cBe[co] - mean * sc;
        float v0 = a0 * sc + sh, v1 = a1 * sc + sh, v2 = a2 * sc + sh;
        float* o = g_c + (b * 512 + co) * 3;
        o[0] = v0 >= 0.f ? v0 : 0.2f * v0;
        o[1] = v1 >= 0.f ? v1 : 0.2f * v1;
        o[2] = v2 >= 0.f ? v2 : 0.2f * v2;
    } else {
        int bi = blockIdx.x - 512;
        int s_ = bi >> 7, co = bi & 127;
        const float* W  = s_ ? wW  : hW;
        const float* Bi = s_ ? wB  : hB;
        const float* G  = s_ ? wG  : hG;
        const float* Be = s_ ? wBe : hBe;
        __shared__ float ws[256 * 16];
        for (int i = b; i < 256 * 16; i += 256)
            ws[i] = W[(i >> 4) * 128 * 16 + co * 16 + (i & 15)];
        __syncthreads();
        float acc[16];
        float bv = Bi[co];
        #pragma unroll
        for (int t = 0; t < 16; t++) acc[t] = bv;
        for (int ci = 0; ci < 256; ci++) {
            float x = g_latent[ci * 256 + b];
            const float4* w4 = (const float4*)(ws + ci * 16);
            float4 wa = w4[0], wb = w4[1], wc = w4[2], wd = w4[3];
            acc[0] += x * wa.x; acc[1] += x * wa.y; acc[2]  += x * wa.z; acc[3]  += x * wa.w;
            acc[4] += x * wb.x; acc[5] += x * wb.y; acc[6]  += x * wb.z; acc[7]  += x * wb.w;
            acc[8] += x * wc.x; acc[9] += x * wc.y; acc[10] += x * wc.z; acc[11] += x * wc.w;
            acc[12]+= x * wd.x; acc[13]+= x * wd.y; acc[14] += x * wd.z; acc[15] += x * wd.w;
        }
        float s = 0.f, ss = 0.f;
        #pragma unroll
        for (int t = 0; t < 16; t++) { s += acc[t]; ss += acc[t] * acc[t]; }
        reduce2_256(s, ss);
        const float invN = 1.f / (256.f * 16.f);
        float mean = s * invN, var = ss * invN - mean * mean;
        float sc = G[co] * rsqrtf(var + 1e-5f);
        float sh = Be[co] - mean * sc;
        bf16* xh = g_x2hi[s_];
        bf16* xl = g_x2lo[s_];
        #pragma unroll
        for (int t = 0; t < 16; t++) {
            float v = acc[t] * sc + sh;
            v = v >= 0.f ? v : 0.2f * v;
            bf16 h, l;
            bf16split(v, h, l);
            int idx = (b * 16 + t) * 128 + co;
            xh[idx] = h;
            xl[idx] = l;
        }
    }
}

// ---------------------------------------------------------------------------
// Stage 3: convT16 GEMM + overlap-add fold + BN partials. grid (32,32,2).
// ---------------------------------------------------------------------------
__global__ void __launch_bounds__(256)
k_gemm16(const float* __restrict__ hB2, const float* __restrict__ wB2) {
    extern __shared__ char smraw[];
    float* Zt = (float*)smraw;
    int s_ = blockIdx.z;
    gemm_bf16x3<128>(g_x2hi[s_], g_x2lo[s_], g_w2hi[s_], g_w2lo[s_],
                     blockIdx.y * 128, blockIdx.x * 128, 4096, smraw, Zt);

    const float* Bi = s_ ? wB2 : hB2;
    int pair = threadIdx.x >> 2, sub = threadIdx.x & 3;
    int bb = pair >> 3, cc = pair & 7;
    int b  = blockIdx.y * 8 + bb;
    int co = blockIdx.x * 8 + cc;
    float bias = Bi[co];
    float psum = 0.f, psq = 0.f;
    float* yo = g_y2 + s_ * (256 * 256 * 32) + (b * 256 + co) * 32;
    const float* zrow = Zt + (bb * 16) * ZLD + cc * 16;
    #pragma unroll
    for (int ti = 0; ti < 8; ti++) {
        int t = sub + ti * 4;
        float v = 0.f;
        if (t < 31) {
            #pragma unroll
            for (int k = 0; k < 16; k++) {
                int s2 = t - k;
                if (s2 >= 0 && s2 < 16) v += zrow[s2 * ZLD + k];
            }
            v += bias;
        }
        yo[t] = v;
        psum += v;
        psq  += v * v;
    }
    psum += __shfl_down_sync(0xffffffffu, psum, 2, 4);
    psum += __shfl_down_sync(0xffffffffu, psum, 1, 4);
    psq  += __shfl_down_sync(0xffffffffu, psq, 2, 4);
    psq  += __shfl_down_sync(0xffffffffu, psq, 1, 4);
    if (sub == 0) {
        g_psum[s_ * 65536 + b * 256 + co] = psum;
        g_psq [s_ * 65536 + b * 256 + co] = psq;
    }
}

// ---------------------------------------------------------------------------
// Stage 3b: BN partial reduce -> scale/shift. grid 16 x 256.
// ---------------------------------------------------------------------------
__global__ void __launch_bounds__(256)
k_bnstat(const float* __restrict__ hG, const float* __restrict__ hBe,
         const float* __restrict__ wG, const float* __restrict__ wBe) {
    int s_  = blockIdx.x >> 3;
    int co0 = (blockIdx.x & 7) * 32;
    int col = threadIdx.x & 31, bp = threadIdx.x >> 5;
    const float* ps = g_psum + s_ * 65536 + co0 + col;
    const float* pq = g_psq  + s_ * 65536 + co0 + col;
    float sum = 0.f, sq = 0.f;
    #pragma unroll 8
    for (int i = 0; i < 32; i++) {
        int b = bp + 8 * i;
        sum += ps[b * 256];
        sq  += pq[b * 256];
    }
    __shared__ float ssum[8][32], ssq[8][32];
    ssum[bp][col] = sum; ssq[bp][col] = sq;
    __syncthreads();
    if (bp == 0) {
        #pragma unroll
        for (int r = 1; r < 8; r++) { sum += ssum[r][col]; sq += ssq[r][col]; }
        const float* G  = s_ ? wG  : hG;
        const float* Be = s_ ? wBe : hBe;
        int co = co0 + col;
        const float invN = 1.f / (256.f * 31.f);
        float mean = sum * invN, var = sq * invN - mean * mean;
        float sc = G[co] * rsqrtf(var + 1e-5f);
        g_sc[s_ * 256 + co] = sc;
        g_sh[s_ * 256 + co] = Be[co] - mean * sc;
    }
}

// ---------------------------------------------------------------------------
// Stage 4a: X3 prep — BN+lrelu on y2, transpose to [(b,t)][ci], bf16 split.
// grid 512 (s,b); 256 threads = ci.
// ---------------------------------------------------------------------------
__global__ void __launch_bounds__(256)
k_xprep() {
    int s_ = blockIdx.x >> 8, b = blockIdx.x & 255, tid = threadIdx.x;
    __shared__ float scs[256], shs[256];
    __shared__ float Xs[256 * 33];
    scs[tid] = g_sc[s_ * 256 + tid];
    shs[tid] = g_sh[s_ * 256 + tid];
    __syncthreads();
    const float4* in4 = (const float4*)(g_y2 + s_ * (256 * 256 * 32) + b * 8192);
    #pragma unroll
    for (int r = 0; r < 8; r++) {
        int i = tid + 256 * r;
        float4 v = in4[i];
        int ci = i >> 3;
        float sc = scs[ci], sh = shs[ci];
        float x0 = v.x * sc + sh; x0 = x0 >= 0.f ? x0 : 0.2f * x0;
        float x1 = v.y * sc + sh; x1 = x1 >= 0.f ? x1 : 0.2f * x1;
        float x2 = v.z * sc + sh; x2 = x2 >= 0.f ? x2 : 0.2f * x2;
        float x3 = v.w * sc + sh; x3 = x3 >= 0.f ? x3 : 0.2f * x3;
        if ((i & 7) == 7) x3 = 0.f;                      // t==31 zero row
        int base = ci * 33 + (i & 7) * 4;
        Xs[base] = x0; Xs[base + 1] = x1; Xs[base + 2] = x2; Xs[base + 3] = x3;
    }
    __syncthreads();
    bf16* xh = g_x3hi[s_] + (size_t)b * 32 * 256 + tid;
    bf16* xl = g_x3lo[s_] + (size_t)b * 32 * 256 + tid;
    #pragma unroll
    for (int t = 0; t < 32; t++) {
        bf16 h, l;
        bf16split(Xs[tid * 33 + t], h, l);
        xh[t * 256] = h;
        xl[t * 256] = l;
    }
}

// ---------------------------------------------------------------------------
// Stage 4b: convT2 GEMM + fold + tanh + coalesced store. grid (8,64,2).
// ---------------------------------------------------------------------------
__global__ void __launch_bounds__(256)
k_gemm2(const float* __restrict__ hB3, const float* __restrict__ wB3) {
    extern __shared__ char smraw[];
    float* Zt = (float*)smraw;
    int s_ = blockIdx.z;
    gemm_bf16x3<256>(g_x3hi[s_], g_x3lo[s_], g_w3hi[s_], g_w3lo[s_],
                     blockIdx.y * 128, blockIdx.x * 128, 1024, smraw, Zt);

    const float* Bi = s_ ? wB3 : hB3;
    int tid = threadIdx.x;
    int bb = tid >> 6, co = tid & 63;
    float bias = Bi[blockIdx.x * 64 + co];
    float y[32];
    const float* zb = Zt + (bb * 32) * ZLD;
    #pragma unroll
    for (int t = 0; t < 32; t++) {
        float z = zb[t * ZLD + co * 2] + bias;
        if (t > 0) z += zb[(t - 1) * ZLD + co * 2 + 1];
        y[t] = tanhf(z);
    }
    __syncthreads();
    float* yb = Zt + 128 * ZLD;
    #pragma unroll
    for (int t = 0; t < 32; t++) yb[(bb * 64 + co) * 36 + t] = y[t];
    __syncthreads();
    #pragma unroll
    for (int b2 = 0; b2 < 4; b2++) {
        float* o = g_o3 + s_ * (256 * 512 * 32)
                 + (((blockIdx.y * 4 + b2) * 512) + blockIdx.x * 64) * 32;
        for (int i = tid; i < 2048; i += 256)
            o[i] = yb[(b2 * 64 + (i >> 5)) * 36 + (i & 31)];
    }
}

// ---------------------------------------------------------------------------
// Stage 5: out[b,ch,y,x] = sum_r c[b,r,ch]*coef[r] * h[b,r,y] * w[b,r,x]
// ---------------------------------------------------------------------------
__global__ void k_final(const float* __restrict__ coef, float* __restrict__ out) {
    int b = blockIdx.x, tid = threadIdx.x;
    int y = tid >> 5, x = tid & 31;
    __shared__ float shh[32 * 32], shw[32 * 32], shc[32 * 3];
    float a0 = 0.f, a1 = 0.f, a2 = 0.f;
    int ri = tid >> 5, rp = tid & 31;
    for (int r0 = 0; r0 < 512; r0 += 32) {
        shh[tid] = g_o3[                 (b * 512 + r0 + ri) * 32 + rp];
        shw[tid] = g_o3[256 * 512 * 32 + (b * 512 + r0 + ri) * 32 + rp];
        if (tid < 96) {
            int rr = tid / 3, c3 = tid % 3;
            shc[tid] = g_c[(b * 512 + r0 + rr) * 3 + c3] * coef[r0 + rr];
        }
        __syncthreads();
        #pragma unroll
        for (int i = 0; i < 32; i++) {
            float p = shh[i * 32 + y] * shw[i * 32 + x];
            a0 += shc[i * 3 + 0] * p;
            a1 += shc[i * 3 + 1] * p;
            a2 += shc[i * 3 + 2] * p;
        }
        __syncthreads();
    }
    out[((b * 3 + 0) * 32 + y) * 32 + x] = a0;
    out[((b * 3 + 1) * 32 + y) * 32 + x] = a1;
    out[((b * 3 + 2) * 32 + y) * 32 + x] = a2;
}

// ---------------------------------------------------------------------------
extern "C" void kernel_launch(void* const* d_in, const int* in_sizes, int n_in,
                              void* d_out, int out_size) {
    const float* noise  = (const float*)d_in[0];
    const int*   label  = (const int*)  d_in[1];
    const float* lin_w  = (const float*)d_in[2];
    const float* lin_b  = (const float*)d_in[3];
    const float* bn0_g  = (const float*)d_in[4];
    const float* bn0_b  = (const float*)d_in[5];
    const float* emb    = (const float*)d_in[6];
    const float* c_w1   = (const float*)d_in[7];
    const float* c_b1   = (const float*)d_in[8];
    const float* c_g1   = (const float*)d_in[9];
    const float* c_be1  = (const float*)d_in[10];
    const float* h_w1   = (const float*)d_in[11];
    const float* h_b1   = (const float*)d_in[12];
    const float* h_g1   = (const float*)d_in[13];
    const float* h_be1  = (const float*)d_in[14];
    const float* h_w2   = (const float*)d_in[15];
    const float* h_b2   = (const float*)d_in[16];
    const float* h_g2   = (const float*)d_in[17];
    const float* h_be2  = (const float*)d_in[18];
    const float* h_w3   = (const float*)d_in[19];
    const float* h_b3   = (const float*)d_in[20];
    const float* w_w1   = (const float*)d_in[21];
    const float* w_b1   = (const float*)d_in[22];
    const float* w_g1   = (const float*)d_in[23];
    const float* w_be1  = (const float*)d_in[24];
    const float* w_w2   = (const float*)d_in[25];
    const float* w_b2   = (const float*)d_in[26];
    const float* w_g2   = (const float*)d_in[27];
    const float* w_be2  = (const float*)d_in[28];
    const float* w_w3   = (const float*)d_in[29];
    const float* w_b3   = (const float*)d_in[30];
    const float* coef   = (const float*)d_in[31];
    float* out = (float*)d_out;

    cudaFuncSetAttribute(k_gemm16, cudaFuncAttributeMaxDynamicSharedMemorySize, SM_G16_B);
    cudaFuncSetAttribute(k_gemm2,  cudaFuncAttributeMaxDynamicSharedMemorySize, SM_G2_B);

    k_wsplit2<<<dim3(2048, 2), 256>>>(h_w2, w_w2);
    k_wsplit3<<<dim3(1024, 2), 256>>>(h_w3, w_w3);
    k_latent <<<256, 256>>>(noise, label, lin_w, lin_b, bn0_g, bn0_b, emb);
    k_conv1  <<<768, 256>>>(c_w1, c_b1, c_g1, c_be1,
                            h_w1, h_b1, h_g1, h_be1,
                            w_w1, w_b1, w_g1, w_be1);
    k_gemm16 <<<dim3(32, 32, 2), 256, SM_G16_B>>>(h_b2, w_b2);
    k_bnstat <<<16,  256>>>(h_g2, h_be2, w_g2, w_be2);
    k_xprep  <<<512, 256>>>();
    k_gemm2  <<<dim3(8, 64, 2), 256, SM_G2_B>>>(h_b3, w_b3);
    k_final  <<<256, 1024>>>(coef, out);
}

// round 8
// speedup vs baseline: 2.3546x; 1.0842x over previous
#include <cuda_runtime.h>
#include <cuda_bf16.h>
#include <mma.h>
#include <math.h>

using namespace nvcuda;
typedef __nv_bfloat16 bf16;

// ---------------------------------------------------------------------------
// B=256, RANK=512, R4=128, R2=256
// conv1   GEMM: Y[b][n]              = latent @ W1cat  M=256  N=5632 K=256
// convT16 GEMM: Z[(b*16+s2)][(co,k)] = X2 @ W2         M=4096 N=4096 K=128
// convT2  GEMM: Z[(b*32+t)][(co,k)]  = X3 @ W3         M=8192 N=1024 K=256
// All bf16x3 (hi*hi + hi*lo + lo*hi, fp32 accumulate).
// ---------------------------------------------------------------------------

__device__ __align__(16) bf16 g_lathi[256 * 256];      // [b][ci]
__device__ __align__(16) bf16 g_latlo[256 * 256];
__device__ __align__(16) bf16 g_w1hi[256 * 5632];      // [ci][n]  c|h|w concat
__device__ __align__(16) bf16 g_w1lo[256 * 5632];
__device__ float g_bias1[5632];
__device__ float g_craw[256 * 1536];                   // conv1 c raw (bias incl)
__device__ float g_x2raw[2][4096 * 128];               // [(b,s2)][ci] raw (bias incl)
__device__ float g_p1sum[4][5632];
__device__ float g_p1sq [4][5632];
__device__ float g_sc1c[512], g_sh1c[512];
__device__ float g_sc1[2 * 128], g_sh1[2 * 128];       // h/w BN1 per ci
__device__ float g_c[256 * 512 * 3];                   // [b][r][3]
__device__ __align__(16) bf16 g_w2hi[2][128 * 4096];
__device__ __align__(16) bf16 g_w2lo[2][128 * 4096];
__device__ __align__(16) bf16 g_w3hi[2][256 * 1024];
__device__ __align__(16) bf16 g_w3lo[2][256 * 1024];
__device__ float g_y2[2 * 256 * 256 * 32];             // raw conv2 out, t=31 pad
__device__ __align__(16) bf16 g_x3hi[2][8192 * 256];
__device__ __align__(16) bf16 g_x3lo[2][8192 * 256];
__device__ float g_psum[2 * 256 * 256];
__device__ float g_psq [2 * 256 * 256];
__device__ float g_sc[2 * 256];
__device__ float g_sh[2 * 256];
__device__ float g_o3[2 * 256 * 512 * 32];             // [s][b][r][32]

__device__ __forceinline__ void bf16split(float x, bf16& h, bf16& l) {
    h = __float2bfloat16(x);
    l = __float2bfloat16(x - __bfloat162float(h));
}

constexpr int ALD = 40;
constexpr int BLD = 136;
constexpr int ZLD = 132;
constexpr int A_ELEMS = 128 * ALD;
constexpr int B_ELEMS = 32 * BLD;
constexpr int SM_G16_B = 128 * ZLD * 4;                    // 67584
constexpr int SM_G2_B  = 128 * ZLD * 4 + 256 * 36 * 4;     // 104448

__device__ __forceinline__ void reduce2_256(float& s, float& ss) {
    __shared__ float rs[8], rss[8];
    #pragma unroll
    for (int o = 16; o > 0; o >>= 1) {
        s  += __shfl_down_sync(0xffffffffu, s,  o);
        ss += __shfl_down_sync(0xffffffffu, ss, o);
    }
    int wid = threadIdx.x >> 5, lane = threadIdx.x & 31;
    if (lane == 0) { rs[wid] = s; rss[wid] = ss; }
    __syncthreads();
    if (threadIdx.x < 32) {
        float a = lane < 8 ? rs[lane] : 0.f;
        float b = lane < 8 ? rss[lane] : 0.f;
        #pragma unroll
        for (int o = 4; o > 0; o >>= 1) {
            a += __shfl_down_sync(0xffffffffu, a, o);
            b += __shfl_down_sync(0xffffffffu, b, o);
        }
        if (lane == 0) { rs[0] = a; rss[0] = b; }
    }
    __syncthreads();
    s = rs[0]; ss = rss[0];
}

// ---------------------------------------------------------------------------
// bf16x3 128x128 block GEMM; 8 warps as 4(m) x 2(n), warp tile 32x64.
// Result to Zt (f32, ZLD); Zt aliases the loader buffers.
// ---------------------------------------------------------------------------
template<int KTOT>
__device__ __forceinline__ void gemm_bf16x3(
    const bf16* __restrict__ Ahi, const bf16* __restrict__ Alo,
    const bf16* __restrict__ Bhi, const bf16* __restrict__ Blo,
    int m0, int n0, int ldb, char* smraw, float* Zt)
{
    bf16* sAh = (bf16*)smraw;
    bf16* sAl = sAh + A_ELEMS;
    bf16* sBh = sAl + A_ELEMS;
    bf16* sBl = sBh + B_ELEMS;
    int tid = threadIdx.x, w = tid >> 5;
    int mw = w >> 1, nw = w & 1;

    wmma::fragment<wmma::accumulator, 16, 16, 16, float> c[2][4];
    #pragma unroll
    for (int i = 0; i < 2; i++)
        #pragma unroll
        for (int j = 0; j < 4; j++) wmma::fill_fragment(c[i][j], 0.f);

    for (int kc = 0; kc < KTOT; kc += 32) {
        __syncthreads();
        #pragma unroll
        for (int r = 0; r < 2; r++) {
            int idx = tid + 256 * r;
            int row = idx >> 2, seg = (idx & 3) * 8;
            *(uint4*)(sAh + row * ALD + seg) =
                *(const uint4*)(Ahi + (size_t)(m0 + row) * KTOT + kc + seg);
            *(uint4*)(sAl + row * ALD + seg) =
                *(const uint4*)(Alo + (size_t)(m0 + row) * KTOT + kc + seg);
        }
        #pragma unroll
        for (int r = 0; r < 2; r++) {
            int idx = tid + 256 * r;
            int row = idx >> 4, seg = (idx & 15) * 8;
            *(uint4*)(sBh + row * BLD + seg) =
                *(const uint4*)(Bhi + (size_t)(kc + row) * ldb + n0 + seg);
            *(uint4*)(sBl + row * BLD + seg) =
                *(const uint4*)(Blo + (size_t)(kc + row) * ldb + n0 + seg);
        }
        __syncthreads();
        #pragma unroll
        for (int k0 = 0; k0 < 32; k0 += 16) {
            wmma::fragment<wmma::matrix_a, 16, 16, 16, bf16, wmma::row_major> ah[2], al[2];
            #pragma unroll
            for (int i = 0; i < 2; i++) {
                wmma::load_matrix_sync(ah[i], sAh + (mw * 32 + i * 16) * ALD + k0, ALD);
                wmma::load_matrix_sync(al[i], sAl + (mw * 32 + i * 16) * ALD + k0, ALD);
            }
            #pragma unroll
            for (int j = 0; j < 4; j++) {
                wmma::fragment<wmma::matrix_b, 16, 16, 16, bf16, wmma::row_major> bh, bl;
                wmma::load_matrix_sync(bh, sBh + k0 * BLD + nw * 64 + j * 16, BLD);
                wmma::load_matrix_sync(bl, sBl + k0 * BLD + nw * 64 + j * 16, BLD);
                #pragma unroll
                for (int i = 0; i < 2; i++) {
                    wmma::mma_sync(c[i][j], ah[i], bh, c[i][j]);
                    wmma::mma_sync(c[i][j], ah[i], bl, c[i][j]);
                    wmma::mma_sync(c[i][j], al[i], bh, c[i][j]);
                }
            }
        }
    }
    __syncthreads();
    #pragma unroll
    for (int i = 0; i < 2; i++)
        #pragma unroll
        for (int j = 0; j < 4; j++)
            wmma::store_matrix_sync(Zt + (mw * 32 + i * 16) * ZLD + nw * 64 + j * 16,
                                    c[i][j], ZLD, wmma::mem_row_major);
    __syncthreads();
}

// ---------------------------------------------------------------------------
// Stage 1: latent row b: [lrelu(BN0) ; emb[label]] -> bf16 hi/lo [b][ci].
// ---------------------------------------------------------------------------
__global__ void k_latent(const float* __restrict__ noise, const int* __restrict__ label,
                         const float* __restrict__ lin_w, const float* __restrict__ lin_b,
                         const float* __restrict__ g,     const float* __restrict__ be,
                         const float* __restrict__ emb) {
    int j = blockIdx.x, b = threadIdx.x;
    if (j >= 128) {
        int jj = j - 128;
        bf16 h, l;
        bf16split(emb[label[b] * 128 + jj], h, l);
        g_lathi[b * 256 + 128 + jj] = h;
        g_latlo[b * 256 + 128 + jj] = l;
        return;
    }
    __shared__ float wsm[100];
    if (b < 100) wsm[b] = lin_w[j * 100 + b];
    __syncthreads();
    float acc = lin_b[j];
    const float* nb = noise + b * 100;
    #pragma unroll 4
    for (int i = 0; i < 100; i++) acc += nb[i] * wsm[i];
    float s = acc, ss = acc * acc;
    reduce2_256(s, ss);
    float mean = s * (1.f / 256.f);
    float var  = ss * (1.f / 256.f) - mean * mean;
    float sc   = g[j] * rsqrtf(var + 1e-5f);
    float v    = (acc - mean) * sc + be[j];
    v = v >= 0.f ? v : 0.01f * v;
    bf16 h, l;
    bf16split(v, h, l);
    g_lathi[b * 256 + j] = h;
    g_latlo[b * 256 + j] = l;
}

// ---------------------------------------------------------------------------
// Weight prep.
// ---------------------------------------------------------------------------
__global__ void k_w1split(const float* __restrict__ cW, const float* __restrict__ hW,
                          const float* __restrict__ wW) {
    int i = blockIdx.x * 256 + threadIdx.x;          // 256*5632
    int ci = i / 5632, n = i % 5632;
    float x;
    if (n < 1536)      x = cW[ci * 1536 + n];
    else if (n < 3584) x = hW[ci * 2048 + n - 1536];
    else               x = wW[ci * 2048 + n - 3584];
    bf16 h, l;
    bf16split(x, h, l);
    g_w1hi[i] = h;
    g_w1lo[i] = l;
}
__global__ void k_bias1(const float* __restrict__ cB, const float* __restrict__ hB,
                        const float* __restrict__ wB) {
    int n = blockIdx.x * 256 + threadIdx.x;
    float v;
    if (n < 1536)      v = cB[n / 3];
    else if (n < 3584) v = hB[(n - 1536) >> 4];
    else               v = wB[(n - 3584) >> 4];
    g_bias1[n] = v;
}
__global__ void k_wsplit2(const float* __restrict__ hW2, const float* __restrict__ wW2) {
    int s_ = blockIdx.y;
    int i = blockIdx.x * 256 + threadIdx.x;
    bf16 h, l;
    bf16split((s_ ? wW2 : hW2)[i], h, l);
    g_w2hi[s_][i] = h;
    g_w2lo[s_][i] = l;
}
__global__ void k_wsplit3(const float* __restrict__ hW3, const float* __restrict__ wW3) {
    int s_ = blockIdx.y;
    int i = blockIdx.x * 256 + threadIdx.x;
    bf16 h, l;
    bf16split((s_ ? wW3 : hW3)[i], h, l);
    g_w3hi[s_][i] = h;
    g_w3lo[s_][i] = l;
}

// ---------------------------------------------------------------------------
// Stage 2: conv1 GEMM. grid (44, 2). Epilogue: +bias, write raw, col partials.
// ---------------------------------------------------------------------------
__global__ void __launch_bounds__(256)
k_gemm1() {
    extern __shared__ char smraw[];
    float* Zt = (float*)smraw;
    int n0 = blockIdx.x * 128, m0 = blockIdx.y * 128;
    gemm_bf16x3<256>(g_lathi, g_latlo, g_w1hi, g_w1lo, m0, n0, 5632, smraw, Zt);

    __shared__ float sbias[128];
    int tid = threadIdx.x;
    if (tid < 128) sbias[tid] = g_bias1[n0 + tid];
    __syncthreads();

    if (n0 < 1536) {                                  // c branch raw
        for (int r = 0; r < 64; r++) {
            int i = tid + 256 * r;
            int row = i >> 7, col = i & 127;
            float y = Zt[row * ZLD + col] + sbias[col];
            Zt[row * ZLD + col] = y;
            g_craw[(m0 + row) * 1536 + n0 + col] = y;
        }
    } else {                                          // h/w -> X2 layout raw
        int s_ = n0 >= 3584;
        int cobase = (n0 - (s_ ? 3584 : 1536)) >> 4;
        for (int r = 0; r < 64; r++) {
            int i = tid + 256 * r;
            int row = i >> 7, col = i & 127;
            float y = Zt[row * ZLD + col] + sbias[col];
            Zt[row * ZLD + col] = y;
            int k = col & 15, co = cobase + (col >> 4);
            g_x2raw[s_][((m0 + row) * 16 + k) * 128 + co] = y;
        }
    }
    __syncthreads();
    int col = tid & 127, half = tid >> 7;
    float sum = 0.f, sq = 0.f;
    for (int r = 0; r < 64; r++) {
        float y = Zt[(half * 64 + r) * ZLD + col];
        sum += y;
        sq  += y * y;
    }
    int p = blockIdx.y * 2 + half;
    g_p1sum[p][n0 + col] = sum;
    g_p1sq [p][n0 + col] = sq;
}

// ---------------------------------------------------------------------------
// Stage 2b: conv1 BN stats. grid 3 x 256.
// ---------------------------------------------------------------------------
__global__ void k_bnstat1(const float* __restrict__ cG, const float* __restrict__ cBe,
                          const float* __restrict__ hG, const float* __restrict__ hBe,
                          const float* __restrict__ wG, const float* __restrict__ wBe) {
    int tid = threadIdx.x;
    if (blockIdx.x < 2) {
        int co = blockIdx.x * 256 + tid;
        float sum = 0.f, sq = 0.f;
        #pragma unroll
        for (int p = 0; p < 4; p++)
            #pragma unroll
            for (int kk = 0; kk < 3; kk++) {
                sum += g_p1sum[p][co * 3 + kk];
                sq  += g_p1sq [p][co * 3 + kk];
            }
        const float invN = 1.f / 768.f;
        float mean = sum * invN, var = sq * invN - mean * mean;
        float sc = cG[co] * rsqrtf(var + 1e-5f);
        g_sc1c[co] = sc;
        g_sh1c[co] = cBe[co] - mean * sc;
    } else {
        int s_ = tid >> 7, co = tid & 127;
        const float* G  = s_ ? wG  : hG;
        const float* Be = s_ ? wBe : hBe;
        int base = 1536 + s_ * 2048 + co * 16;
        float sum = 0.f, sq = 0.f;
        #pragma unroll
        for (int p = 0; p < 4; p++)
            for (int kk = 0; kk < 16; kk++) {
                sum += g_p1sum[p][base + kk];
                sq  += g_p1sq [p][base + kk];
            }
        const float invN = 1.f / 4096.f;
        float mean = sum * invN, var = sq * invN - mean * mean;
        float sc = G[co] * rsqrtf(var + 1e-5f);
        g_sc1[s_ * 128 + co] = sc;
        g_sh1[s_ * 128 + co] = Be[co] - mean * sc;
    }
}

// ---------------------------------------------------------------------------
// Stage 2c: g_c = lrelu(BN(craw)). grid (6, 256).
// ---------------------------------------------------------------------------
__global__ void k_capply() {
    int n = blockIdx.x * 256 + threadIdx.x;
    int b = blockIdx.y;
    int co = n / 3;
    float v = g_craw[b * 1536 + n] * g_sc1c[co] + g_sh1c[co];
    g_c[b * 1536 + n] = v >= 0.f ? v : 0.2f * v;
}

// ---------------------------------------------------------------------------
// Stage 3: convT16 GEMM with BN+lrelu+split fused into the A loader.
// grid (32,32,2), 256 threads.
// ---------------------------------------------------------------------------
__global__ void __launch_bounds__(256)
k_gemm16(const float* __restrict__ hB2, const float* __restrict__ wB2) {
    extern __shared__ char smraw[];
    float* Zt = (float*)smraw;
    bf16* sAh = (bf16*)smraw;
    bf16* sAl = sAh + A_ELEMS;
    bf16* sBh = sAl + A_ELEMS;
    bf16* sBl = sBh + B_ELEMS;
    __shared__ float ssc[128], ssh[128];
    int s_ = blockIdx.z;
    int m0 = blockIdx.y * 128, n0 = blockIdx.x * 128;
    int tid = threadIdx.x, w = tid >> 5, mw = w >> 1, nw = w & 1;
    if (tid < 128) {
        ssc[tid] = g_sc1[s_ * 128 + tid];
        ssh[tid] = g_sh1[s_ * 128 + tid];
    }
    const bf16* Bhi = g_w2hi[s_];
    const bf16* Blo = g_w2lo[s_];
    const float* Xr = g_x2raw[s_];

    wmma::fragment<wmma::accumulator, 16, 16, 16, float> c[2][4];
    #pragma unroll
    for (int i = 0; i < 2; i++)
        #pragma unroll
        for (int j = 0; j < 4; j++) wmma::fill_fragment(c[i][j], 0.f);

    for (int kc = 0; kc < 128; kc += 32) {
        __syncthreads();
        #pragma unroll
        for (int r = 0; r < 2; r++) {                     // A: fp32 + BN + split
            int idx = tid + 256 * r;
            int row = idx >> 2, seg = (idx & 3) * 8;
            const float* src = Xr + (size_t)(m0 + row) * 128 + kc + seg;
            float4 fa = *(const float4*)src;
            float4 fb = *(const float4*)(src + 4);
            float vs[8] = {fa.x, fa.y, fa.z, fa.w, fb.x, fb.y, fb.z, fb.w};
            __align__(16) bf16 hs[8], ls[8];
            #pragma unroll
            for (int j = 0; j < 8; j++) {
                int ci = kc + seg + j;
                float y = vs[j] * ssc[ci] + ssh[ci];
                y = y >= 0.f ? y : 0.2f * y;
                bf16split(y, hs[j], ls[j]);
            }
            *(uint4*)(sAh + row * ALD + seg) = *(uint4*)hs;
            *(uint4*)(sAl + row * ALD + seg) = *(uint4*)ls;
        }
        #pragma unroll
        for (int r = 0; r < 2; r++) {                     // B: bf16 direct
            int idx = tid + 256 * r;
            int row = idx >> 4, seg = (idx & 15) * 8;
            *(uint4*)(sBh + row * BLD + seg) =
                *(const uint4*)(Bhi + (size_t)(kc + row) * 4096 + n0 + seg);
            *(uint4*)(sBl + row * BLD + seg) =
                *(const uint4*)(Blo + (size_t)(kc + row) * 4096 + n0 + seg);
        }
        __syncthreads();
        #pragma unroll
        for (int k0 = 0; k0 < 32; k0 += 16) {
            wmma::fragment<wmma::matrix_a, 16, 16, 16, bf16, wmma::row_major> ah[2], al[2];
            #pragma unroll
            for (int i = 0; i < 2; i++) {
                wmma::load_matrix_sync(ah[i], sAh + (mw * 32 + i * 16) * ALD + k0, ALD);
                wmma::load_matrix_sync(al[i], sAl + (mw * 32 + i * 16) * ALD + k0, ALD);
            }
            #pragma unroll
            for (int j = 0; j < 4; j++) {
                wmma::fragment<wmma::matrix_b, 16, 16, 16, bf16, wmma::row_major> bh, bl;
                wmma::load_matrix_sync(bh, sBh + k0 * BLD + nw * 64 + j * 16, BLD);
                wmma::load_matrix_sync(bl, sBl + k0 * BLD + nw * 64 + j * 16, BLD);
                #pragma unroll
                for (int i = 0; i < 2; i++) {
                    wmma::mma_sync(c[i][j], ah[i], bh, c[i][j]);
                    wmma::mma_sync(c[i][j], ah[i], bl, c[i][j]);
                    wmma::mma_sync(c[i][j], al[i], bh, c[i][j]);
                }
            }
        }
    }
    __syncthreads();
    #pragma unroll
    for (int i = 0; i < 2; i++)
        #pragma unroll
        for (int j = 0; j < 4; j++)
            wmma::store_matrix_sync(Zt + (mw * 32 + i * 16) * ZLD + nw * 64 + j * 16,
                                    c[i][j], ZLD, wmma::mem_row_major);
    __syncthreads();

    // fold epilogue
    const float* Bi = s_ ? wB2 : hB2;
    int pair = tid >> 2, sub = tid & 3;
    int bb = pair >> 3, cc = pair & 7;
    int b  = blockIdx.y * 8 + bb;
    int co = blockIdx.x * 8 + cc;
    float bias = Bi[co];
    float psum = 0.f, psq = 0.f;
    float* yo = g_y2 + s_ * (256 * 256 * 32) + (b * 256 + co) * 32;
    const float* zrow = Zt + (bb * 16) * ZLD + cc * 16;
    #pragma unroll
    for (int ti = 0; ti < 8; ti++) {
        int t = sub + ti * 4;
        float v = 0.f;
        if (t < 31) {
            #pragma unroll
            for (int k = 0; k < 16; k++) {
                int s2 = t - k;
                if (s2 >= 0 && s2 < 16) v += zrow[s2 * ZLD + k];
            }
            v += bias;
        }
        yo[t] = v;
        psum += v;
        psq  += v * v;
    }
    psum += __shfl_down_sync(0xffffffffu, psum, 2, 4);
    psum += __shfl_down_sync(0xffffffffu, psum, 1, 4);
    psq  += __shfl_down_sync(0xffffffffu, psq, 2, 4);
    psq  += __shfl_down_sync(0xffffffffu, psq, 1, 4);
    if (sub == 0) {
        g_psum[s_ * 65536 + b * 256 + co] = psum;
        g_psq [s_ * 65536 + b * 256 + co] = psq;
    }
}

// ---------------------------------------------------------------------------
// Stage 3b: BN2 partial reduce. grid 16 x 256.
// ---------------------------------------------------------------------------
__global__ void __launch_bounds__(256)
k_bnstat(const float* __restrict__ hG, const float* __restrict__ hBe,
         const float* __restrict__ wG, const float* __restrict__ wBe) {
    int s_  = blockIdx.x >> 3;
    int co0 = (blockIdx.x & 7) * 32;
    int col = threadIdx.x & 31, bp = threadIdx.x >> 5;
    const float* ps = g_psum + s_ * 65536 + co0 + col;
    const float* pq = g_psq  + s_ * 65536 + co0 + col;
    float sum = 0.f, sq = 0.f;
    #pragma unroll 8
    for (int i = 0; i < 32; i++) {
        int b = bp + 8 * i;
        sum += ps[b * 256];
        sq  += pq[b * 256];
    }
    __shared__ float ssum[8][32], ssq[8][32];
    ssum[bp][col] = sum; ssq[bp][col] = sq;
    __syncthreads();
    if (bp == 0) {
        #pragma unroll
        for (int r = 1; r < 8; r++) { sum += ssum[r][col]; sq += ssq[r][col]; }
        const float* G  = s_ ? wG  : hG;
        const float* Be = s_ ? wBe : hBe;
        int co = co0 + col;
        const float invN = 1.f / (256.f * 31.f);
        float mean = sum * invN, var = sq * invN - mean * mean;
        float sc = G[co] * rsqrtf(var + 1e-5f);
        g_sc[s_ * 256 + co] = sc;
        g_sh[s_ * 256 + co] = Be[co] - mean * sc;
    }
}

// ---------------------------------------------------------------------------
// Stage 4a: X3 prep — BN+lrelu on y2, transpose to [(b,t)][ci], bf16 split.
// grid 512 (s,b); 256 threads = ci.
// ---------------------------------------------------------------------------
__global__ void __launch_bounds__(256)
k_xprep() {
    int s_ = blockIdx.x >> 8, b = blockIdx.x & 255, tid = threadIdx.x;
    __shared__ float scs[256], shs[256];
    __shared__ float Xs[256 * 33];
    scs[tid] = g_sc[s_ * 256 + tid];
    shs[tid] = g_sh[s_ * 256 + tid];
    __syncthreads();
    const float4* in4 = (const float4*)(g_y2 + s_ * (256 * 256 * 32) + b * 8192);
    #pragma unroll
    for (int r = 0; r < 8; r++) {
        int i = tid + 256 * r;
        float4 v = in4[i];
        int ci = i >> 3;
        float sc = scs[ci], sh = shs[ci];
        float x0 = v.x * sc + sh; x0 = x0 >= 0.f ? x0 : 0.2f * x0;
        float x1 = v.y * sc + sh; x1 = x1 >= 0.f ? x1 : 0.2f * x1;
        float x2 = v.z * sc + sh; x2 = x2 >= 0.f ? x2 : 0.2f * x2;
        float x3 = v.w * sc + sh; x3 = x3 >= 0.f ? x3 : 0.2f * x3;
        if ((i & 7) == 7) x3 = 0.f;
        int base = ci * 33 + (i & 7) * 4;
        Xs[base] = x0; Xs[base + 1] = x1; Xs[base + 2] = x2; Xs[base + 3] = x3;
    }
    __syncthreads();
    bf16* xh = g_x3hi[s_] + (size_t)b * 32 * 256 + tid;
    bf16* xl = g_x3lo[s_] + (size_t)b * 32 * 256 + tid;
    #pragma unroll
    for (int t = 0; t < 32; t++) {
        bf16 h, l;
        bf16split(Xs[tid * 33 + t], h, l);
        xh[t * 256] = h;
        xl[t * 256] = l;
    }
}

// ---------------------------------------------------------------------------
// Stage 4b: convT2 GEMM + fold + tanh + coalesced store. grid (8,64,2).
// ---------------------------------------------------------------------------
__global__ void __launch_bounds__(256)
k_gemm2(const float* __restrict__ hB3, const float* __restrict__ wB3) {
    extern __shared__ char smraw[];
    float* Zt = (float*)smraw;
    int s_ = blockIdx.z;
    gemm_bf16x3<256>(g_x3hi[s_], g_x3lo[s_], g_w3hi[s_], g_w3lo[s_],
                     blockIdx.y * 128, blockIdx.x * 128, 1024, smraw, Zt);

    const float* Bi = s_ ? wB3 : hB3;
    int tid = threadIdx.x;
    int bb = tid >> 6, co = tid & 63;
    float bias = Bi[blockIdx.x * 64 + co];
    float y[32];
    const float* zb = Zt + (bb * 32) * ZLD;
    #pragma unroll
    for (int t = 0; t < 32; t++) {
        float z = zb[t * ZLD + co * 2] + bias;
        if (t > 0) z += zb[(t - 1) * ZLD + co * 2 + 1];
        y[t] = tanhf(z);
    }
    __syncthreads();
    float* yb = Zt + 128 * ZLD;
    #pragma unroll
    for (int t = 0; t < 32; t++) yb[(bb * 64 + co) * 36 + t] = y[t];
    __syncthreads();
    #pragma unroll
    for (int b2 = 0; b2 < 4; b2++) {
        float* o = g_o3 + s_ * (256 * 512 * 32)
                 + (((blockIdx.y * 4 + b2) * 512) + blockIdx.x * 64) * 32;
        for (int i = tid; i < 2048; i += 256)
            o[i] = yb[(b2 * 64 + (i >> 5)) * 36 + (i & 31)];
    }
}

// ---------------------------------------------------------------------------
// Stage 5: out[b,ch,y,x] = sum_r c[b,r,ch]*coef[r] * h[b,r,y] * w[b,r,x]
// ---------------------------------------------------------------------------
__global__ void k_final(const float* __restrict__ coef, float* __restrict__ out) {
    int b = blockIdx.x, tid = threadIdx.x;
    int y = tid >> 5, x = tid & 31;
    __shared__ float shh[32 * 32], shw[32 * 32], shc[32 * 3];
    float a0 = 0.f, a1 = 0.f, a2 = 0.f;
    int ri = tid >> 5, rp = tid & 31;
    for (int r0 = 0; r0 < 512; r0 += 32) {
        shh[tid] = g_o3[                 (b * 512 + r0 + ri) * 32 + rp];
        shw[tid] = g_o3[256 * 512 * 32 + (b * 512 + r0 + ri) * 32 + rp];
        if (tid < 96) {
            int rr = tid / 3, c3 = tid % 3;
            shc[tid] = g_c[(b * 512 + r0 + rr) * 3 + c3] * coef[r0 + rr];
        }
        __syncthreads();
        #pragma unroll
        for (int i = 0; i < 32; i++) {
            float p = shh[i * 32 + y] * shw[i * 32 + x];
            a0 += shc[i * 3 + 0] * p;
            a1 += shc[i * 3 + 1] * p;
            a2 += shc[i * 3 + 2] * p;
        }
        __syncthreads();
    }
    out[((b * 3 + 0) * 32 + y) * 32 + x] = a0;
    out[((b * 3 + 1) * 32 + y) * 32 + x] = a1;
    out[((b * 3 + 2) * 32 + y) * 32 + x] = a2;
}

// ---------------------------------------------------------------------------
extern "C" void kernel_launch(void* const* d_in, const int* in_sizes, int n_in,
                              void* d_out, int out_size) {
    const float* noise  = (const float*)d_in[0];
    const int*   label  = (const int*)  d_in[1];
    const float* lin_w  = (const float*)d_in[2];
    const float* lin_b  = (const float*)d_in[3];
    const float* bn0_g  = (const float*)d_in[4];
    const float* bn0_b  = (const float*)d_in[5];
    const float* emb    = (const float*)d_in[6];
    const float* c_w1   = (const float*)d_in[7];
    const float* c_b1   = (const float*)d_in[8];
    const float* c_g1   = (const float*)d_in[9];
    const float* c_be1  = (const float*)d_in[10];
    const float* h_w1   = (const float*)d_in[11];
    const float* h_b1   = (const float*)d_in[12];
    const float* h_g1   = (const float*)d_in[13];
    const float* h_be1  = (const float*)d_in[14];
    const float* h_w2   = (const float*)d_in[15];
    const float* h_b2   = (const float*)d_in[16];
    const float* h_g2   = (const float*)d_in[17];
    const float* h_be2  = (const float*)d_in[18];
    const float* h_w3   = (const float*)d_in[19];
    const float* h_b3   = (const float*)d_in[20];
    const float* w_w1   = (const float*)d_in[21];
    const float* w_b1   = (const float*)d_in[22];
    const float* w_g1   = (const float*)d_in[23];
    const float* w_be1  = (const float*)d_in[24];
    const float* w_w2   = (const float*)d_in[25];
    const float* w_b2   = (const float*)d_in[26];
    const float* w_g2   = (const float*)d_in[27];
    const float* w_be2  = (const float*)d_in[28];
    const float* w_w3   = (const float*)d_in[29];
    const float* w_b3   = (const float*)d_in[30];
    const float* coef   = (const float*)d_in[31];
    float* out = (float*)d_out;

    cudaFuncSetAttribute(k_gemm1,  cudaFuncAttributeMaxDynamicSharedMemorySize, SM_G16_B);
    cudaFuncSetAttribute(k_gemm16, cudaFuncAttributeMaxDynamicSharedMemorySize, SM_G16_B);
    cudaFuncSetAttribute(k_gemm2,  cudaFuncAttributeMaxDynamicSharedMemorySize, SM_G2_B);

    k_wsplit2<<<dim3(2048, 2), 256>>>(h_w2, w_w2);
    k_wsplit3<<<dim3(1024, 2), 256>>>(h_w3, w_w3);
    k_w1split<<<5632, 256>>>(c_w1, h_w1, w_w1);
    k_bias1  <<<22,   256>>>(c_b1, h_b1, w_b1);
    k_latent <<<256,  256>>>(noise, label, lin_w, lin_b, bn0_g, bn0_b, emb);
    k_gemm1  <<<dim3(44, 2), 256, SM_G16_B>>>();
    k_bnstat1<<<3,    256>>>(c_g1, c_be1, h_g1, h_be1, w_g1, w_be1);
    k_capply <<<dim3(6, 256), 256>>>();
    k_gemm16 <<<dim3(32, 32, 2), 256, SM_G16_B>>>(h_b2, w_b2);
    k_bnstat <<<16,   256>>>(h_g2, h_be2, w_g2, w_be2);
    k_xprep  <<<512,  256>>>();
    k_gemm2  <<<dim3(8, 64, 2), 256, SM_G2_B>>>(h_b3, w_b3);
    k_final  <<<256,  1024>>>(coef, out);
}

// round 9
// speedup vs baseline: 2.5190x; 1.0698x over previous
#include <cuda_runtime.h>
#include <cuda_bf16.h>
#include <mma.h>
#include <math.h>

using namespace nvcuda;
typedef __nv_bfloat16 bf16;

// ---------------------------------------------------------------------------
// B=256, RANK=512, R4=128, R2=256
// conv1   GEMM: Y[b][n]              = latent @ W1cat  M=256  N=5632 K=256
// convT16 GEMM: Z[(b*16+s2)][(co,k)] = X2 @ W2         M=4096 N=4096 K=128
// convT2  GEMM: Z[(b*32+t)][(co,k)]  = X3 @ W3         M=8192 N=1024 K=256
// All bf16x3 (hi*hi + hi*lo + lo*hi, fp32 accumulate).
// ---------------------------------------------------------------------------

__device__ __align__(16) bf16 g_lathi[256 * 256];      // [b][ci]
__device__ __align__(16) bf16 g_latlo[256 * 256];
__device__ __align__(16) bf16 g_w1hi[256 * 5632];      // [ci][n]  c|h|w concat
__device__ __align__(16) bf16 g_w1lo[256 * 5632];
__device__ float g_bias1[5632];
__device__ float g_craw[256 * 1536];                   // conv1 c raw (bias incl)
__device__ float g_x2raw[2][4096 * 128];               // [(b,s2)][ci] raw
__device__ float g_p1sum[4][5632];
__device__ float g_p1sq [4][5632];
__device__ float g_sc1c[512], g_sh1c[512];
__device__ float g_sc1[2 * 128], g_sh1[2 * 128];       // h/w BN1 per ci
__device__ __align__(16) bf16 g_w2hi[2][128 * 4096];
__device__ __align__(16) bf16 g_w2lo[2][128 * 4096];
__device__ __align__(16) bf16 g_w3hi[2][256 * 1024];
__device__ __align__(16) bf16 g_w3lo[2][256 * 1024];
__device__ float g_y2t[2][8192 * 256];                 // raw conv2 out in gemm2-A layout
__device__ float g_psum[2 * 256 * 256];
__device__ float g_psq [2 * 256 * 256];
__device__ float g_sc[2 * 256];
__device__ float g_sh[2 * 256];
__device__ float g_o3[2 * 256 * 512 * 32];             // [s][b][r][32]

__device__ __forceinline__ void bf16split(float x, bf16& h, bf16& l) {
    h = __float2bfloat16(x);
    l = __float2bfloat16(x - __bfloat162float(h));
}

constexpr int ALD = 40;
constexpr int BLD = 136;
constexpr int ZLD = 132;
constexpr int A_ELEMS = 128 * ALD;
constexpr int B_ELEMS = 32 * BLD;
constexpr int SM_G16_B = 128 * ZLD * 4;                    // 67584
constexpr int SM_G2_B  = 128 * ZLD * 4 + 256 * 36 * 4;     // 104448

__device__ __forceinline__ void reduce2_256(float& s, float& ss) {
    __shared__ float rs[8], rss[8];
    #pragma unroll
    for (int o = 16; o > 0; o >>= 1) {
        s  += __shfl_down_sync(0xffffffffu, s,  o);
        ss += __shfl_down_sync(0xffffffffu, ss, o);
    }
    int wid = threadIdx.x >> 5, lane = threadIdx.x & 31;
    if (lane == 0) { rs[wid] = s; rss[wid] = ss; }
    __syncthreads();
    if (threadIdx.x < 32) {
        float a = lane < 8 ? rs[lane] : 0.f;
        float b = lane < 8 ? rss[lane] : 0.f;
        #pragma unroll
        for (int o = 4; o > 0; o >>= 1) {
            a += __shfl_down_sync(0xffffffffu, a, o);
            b += __shfl_down_sync(0xffffffffu, b, o);
        }
        if (lane == 0) { rs[0] = a; rss[0] = b; }
    }
    __syncthreads();
    s = rs[0]; ss = rss[0];
}

// ---------------------------------------------------------------------------
// bf16x3 128x128 block GEMM core (A/B already bf16 in gmem).
// ---------------------------------------------------------------------------
template<int KTOT>
__device__ __forceinline__ void gemm_bf16x3(
    const bf16* __restrict__ Ahi, const bf16* __restrict__ Alo,
    const bf16* __restrict__ Bhi, const bf16* __restrict__ Blo,
    int m0, int n0, int ldb, char* smraw, float* Zt)
{
    bf16* sAh = (bf16*)smraw;
    bf16* sAl = sAh + A_ELEMS;
    bf16* sBh = sAl + A_ELEMS;
    bf16* sBl = sBh + B_ELEMS;
    int tid = threadIdx.x, w = tid >> 5;
    int mw = w >> 1, nw = w & 1;

    wmma::fragment<wmma::accumulator, 16, 16, 16, float> c[2][4];
    #pragma unroll
    for (int i = 0; i < 2; i++)
        #pragma unroll
        for (int j = 0; j < 4; j++) wmma::fill_fragment(c[i][j], 0.f);

    for (int kc = 0; kc < KTOT; kc += 32) {
        __syncthreads();
        #pragma unroll
        for (int r = 0; r < 2; r++) {
            int idx = tid + 256 * r;
            int row = idx >> 2, seg = (idx & 3) * 8;
            *(uint4*)(sAh + row * ALD + seg) =
                *(const uint4*)(Ahi + (size_t)(m0 + row) * KTOT + kc + seg);
            *(uint4*)(sAl + row * ALD + seg) =
                *(const uint4*)(Alo + (size_t)(m0 + row) * KTOT + kc + seg);
        }
        #pragma unroll
        for (int r = 0; r < 2; r++) {
            int idx = tid + 256 * r;
            int row = idx >> 4, seg = (idx & 15) * 8;
            *(uint4*)(sBh + row * BLD + seg) =
                *(const uint4*)(Bhi + (size_t)(kc + row) * ldb + n0 + seg);
            *(uint4*)(sBl + row * BLD + seg) =
                *(const uint4*)(Blo + (size_t)(kc + row) * ldb + n0 + seg);
        }
        __syncthreads();
        #pragma unroll
        for (int k0 = 0; k0 < 32; k0 += 16) {
            wmma::fragment<wmma::matrix_a, 16, 16, 16, bf16, wmma::row_major> ah[2], al[2];
            #pragma unroll
            for (int i = 0; i < 2; i++) {
                wmma::load_matrix_sync(ah[i], sAh + (mw * 32 + i * 16) * ALD + k0, ALD);
                wmma::load_matrix_sync(al[i], sAl + (mw * 32 + i * 16) * ALD + k0, ALD);
            }
            #pragma unroll
            for (int j = 0; j < 4; j++) {
                wmma::fragment<wmma::matrix_b, 16, 16, 16, bf16, wmma::row_major> bh, bl;
                wmma::load_matrix_sync(bh, sBh + k0 * BLD + nw * 64 + j * 16, BLD);
                wmma::load_matrix_sync(bl, sBl + k0 * BLD + nw * 64 + j * 16, BLD);
                #pragma unroll
                for (int i = 0; i < 2; i++) {
                    wmma::mma_sync(c[i][j], ah[i], bh, c[i][j]);
                    wmma::mma_sync(c[i][j], ah[i], bl, c[i][j]);
                    wmma::mma_sync(c[i][j], al[i], bh, c[i][j]);
                }
            }
        }
    }
    __syncthreads();
    #pragma unroll
    for (int i = 0; i < 2; i++)
        #pragma unroll
        for (int j = 0; j < 4; j++)
            wmma::store_matrix_sync(Zt + (mw * 32 + i * 16) * ZLD + nw * 64 + j * 16,
                                    c[i][j], ZLD, wmma::mem_row_major);
    __syncthreads();
}

// ---------------------------------------------------------------------------
// Stage 0: ALL weight prep in one launch. grid 11798 x 256.
//   blocks [0,5632)        : W1 concat split (256*5632)
//   blocks [5632,9728)     : W2 split (2 x 524288)
//   blocks [9728,11776)    : W3 split (2 x 262144)
//   blocks [11776,11798)   : bias1 concat (5632)
// ---------------------------------------------------------------------------
__global__ void k_wprep(const float* __restrict__ cW1, const float* __restrict__ hW1,
                        const float* __restrict__ wW1,
                        const float* __restrict__ cB,  const float* __restrict__ hB,
                        const float* __restrict__ wB,
                        const float* __restrict__ hW2, const float* __restrict__ wW2,
                        const float* __restrict__ hW3, const float* __restrict__ wW3) {
    int blk = blockIdx.x, tid = threadIdx.x;
    if (blk < 5632) {
        int i = blk * 256 + tid;
        int ci = i / 5632, n = i % 5632;
        float x;
        if (n < 1536)      x = cW1[ci * 1536 + n];
        else if (n < 3584) x = hW1[ci * 2048 + n - 1536];
        else               x = wW1[ci * 2048 + n - 3584];
        bf16 h, l; bf16split(x, h, l);
        g_w1hi[i] = h; g_w1lo[i] = l;
    } else if (blk < 9728) {
        int i = (blk - 5632) * 256 + tid;
        int s_ = i >= 524288;
        int j = i - s_ * 524288;
        bf16 h, l; bf16split((s_ ? wW2 : hW2)[j], h, l);
        g_w2hi[s_][j] = h; g_w2lo[s_][j] = l;
    } else if (blk < 11776) {
        int i = (blk - 9728) * 256 + tid;
        int s_ = i >= 262144;
        int j = i - s_ * 262144;
        bf16 h, l; bf16split((s_ ? wW3 : hW3)[j], h, l);
        g_w3hi[s_][j] = h; g_w3lo[s_][j] = l;
    } else {
        int n = (blk - 11776) * 256 + tid;
        if (n < 5632) {
            float v;
            if (n < 1536)      v = cB[n / 3];
            else if (n < 3584) v = hB[(n - 1536) >> 4];
            else               v = wB[(n - 3584) >> 4];
            g_bias1[n] = v;
        }
    }
}

// ---------------------------------------------------------------------------
// Stage 1: latent row b -> bf16 hi/lo [b][ci].
// ---------------------------------------------------------------------------
__global__ void k_latent(const float* __restrict__ noise, const int* __restrict__ label,
                         const float* __restrict__ lin_w, const float* __restrict__ lin_b,
                         const float* __restrict__ g,     const float* __restrict__ be,
                         const float* __restrict__ emb) {
    int j = blockIdx.x, b = threadIdx.x;
    if (j >= 128) {
        int jj = j - 128;
        bf16 h, l;
        bf16split(emb[label[b] * 128 + jj], h, l);
        g_lathi[b * 256 + 128 + jj] = h;
        g_latlo[b * 256 + 128 + jj] = l;
        return;
    }
    __shared__ float wsm[100];
    if (b < 100) wsm[b] = lin_w[j * 100 + b];
    __syncthreads();
    float acc = lin_b[j];
    const float* nb = noise + b * 100;
    #pragma unroll 4
    for (int i = 0; i < 100; i++) acc += nb[i] * wsm[i];
    float s = acc, ss = acc * acc;
    reduce2_256(s, ss);
    float mean = s * (1.f / 256.f);
    float var  = ss * (1.f / 256.f) - mean * mean;
    float sc   = g[j] * rsqrtf(var + 1e-5f);
    float v    = (acc - mean) * sc + be[j];
    v = v >= 0.f ? v : 0.01f * v;
    bf16 h, l;
    bf16split(v, h, l);
    g_lathi[b * 256 + j] = h;
    g_latlo[b * 256 + j] = l;
}

// ---------------------------------------------------------------------------
// Stage 2: conv1 GEMM. grid (44, 2). Epilogue: +bias, raw out, col partials.
// ---------------------------------------------------------------------------
__global__ void __launch_bounds__(256)
k_gemm1() {
    extern __shared__ char smraw[];
    float* Zt = (float*)smraw;
    int n0 = blockIdx.x * 128, m0 = blockIdx.y * 128;
    gemm_bf16x3<256>(g_lathi, g_latlo, g_w1hi, g_w1lo, m0, n0, 5632, smraw, Zt);

    __shared__ float sbias[128];
    int tid = threadIdx.x;
    if (tid < 128) sbias[tid] = g_bias1[n0 + tid];
    __syncthreads();

    if (n0 < 1536) {
        for (int r = 0; r < 64; r++) {
            int i = tid + 256 * r;
            int row = i >> 7, col = i & 127;
            float y = Zt[row * ZLD + col] + sbias[col];
            Zt[row * ZLD + col] = y;
            g_craw[(m0 + row) * 1536 + n0 + col] = y;
        }
    } else {
        int s_ = n0 >= 3584;
        int cobase = (n0 - (s_ ? 3584 : 1536)) >> 4;
        for (int r = 0; r < 64; r++) {
            int i = tid + 256 * r;
            int row = i >> 7, col = i & 127;
            float y = Zt[row * ZLD + col] + sbias[col];
            Zt[row * ZLD + col] = y;
            int k = col & 15, co = cobase + (col >> 4);
            g_x2raw[s_][((m0 + row) * 16 + k) * 128 + co] = y;
        }
    }
    __syncthreads();
    int col = tid & 127, half = tid >> 7;
    float sum = 0.f, sq = 0.f;
    for (int r = 0; r < 64; r++) {
        float y = Zt[(half * 64 + r) * ZLD + col];
        sum += y;
        sq  += y * y;
    }
    int p = blockIdx.y * 2 + half;
    g_p1sum[p][n0 + col] = sum;
    g_p1sq [p][n0 + col] = sq;
}

// ---------------------------------------------------------------------------
// Stage 2b: conv1 BN stats. grid 3 x 256.
// ---------------------------------------------------------------------------
__global__ void k_bnstat1(const float* __restrict__ cG, const float* __restrict__ cBe,
                          const float* __restrict__ hG, const float* __restrict__ hBe,
                          const float* __restrict__ wG, const float* __restrict__ wBe) {
    int tid = threadIdx.x;
    if (blockIdx.x < 2) {
        int co = blockIdx.x * 256 + tid;
        float sum = 0.f, sq = 0.f;
        #pragma unroll
        for (int p = 0; p < 4; p++)
            #pragma unroll
            for (int kk = 0; kk < 3; kk++) {
                sum += g_p1sum[p][co * 3 + kk];
                sq  += g_p1sq [p][co * 3 + kk];
            }
        const float invN = 1.f / 768.f;
        float mean = sum * invN, var = sq * invN - mean * mean;
        float sc = cG[co] * rsqrtf(var + 1e-5f);
        g_sc1c[co] = sc;
        g_sh1c[co] = cBe[co] - mean * sc;
    } else {
        int s_ = tid >> 7, co = tid & 127;
        const float* G  = s_ ? wG  : hG;
        const float* Be = s_ ? wBe : hBe;
        int base = 1536 + s_ * 2048 + co * 16;
        float sum = 0.f, sq = 0.f;
        #pragma unroll
        for (int p = 0; p < 4; p++)
            for (int kk = 0; kk < 16; kk++) {
                sum += g_p1sum[p][base + kk];
                sq  += g_p1sq [p][base + kk];
            }
        const float invN = 1.f / 4096.f;
        float mean = sum * invN, var = sq * invN - mean * mean;
        float sc = G[co] * rsqrtf(var + 1e-5f);
        g_sc1[s_ * 128 + co] = sc;
        g_sh1[s_ * 128 + co] = Be[co] - mean * sc;
    }
}

// ---------------------------------------------------------------------------
// Stage 3: convT16 GEMM, BN1 fused in A loader; epilogue folds + writes raw
// y2 directly in gemm2-A layout [(b*32+t)][co] + BN2 partials.
// grid (32,32,2), 256 threads.
// ---------------------------------------------------------------------------
__global__ void __launch_bounds__(256)
k_gemm16(const float* __restrict__ hB2, const float* __restrict__ wB2) {
    extern __shared__ char smraw[];
    float* Zt = (float*)smraw;
    bf16* sAh = (bf16*)smraw;
    bf16* sAl = sAh + A_ELEMS;
    bf16* sBh = sAl + A_ELEMS;
    bf16* sBl = sBh + B_ELEMS;
    __shared__ float ssc[128], ssh[128];
    int s_ = blockIdx.z;
    int m0 = blockIdx.y * 128, n0 = blockIdx.x * 128;
    int tid = threadIdx.x, w = tid >> 5, mw = w >> 1, nw = w & 1;
    if (tid < 128) {
        ssc[tid] = g_sc1[s_ * 128 + tid];
        ssh[tid] = g_sh1[s_ * 128 + tid];
    }
    const bf16* Bhi = g_w2hi[s_];
    const bf16* Blo = g_w2lo[s_];
    const float* Xr = g_x2raw[s_];

    wmma::fragment<wmma::accumulator, 16, 16, 16, float> c[2][4];
    #pragma unroll
    for (int i = 0; i < 2; i++)
        #pragma unroll
        for (int j = 0; j < 4; j++) wmma::fill_fragment(c[i][j], 0.f);

    for (int kc = 0; kc < 128; kc += 32) {
        __syncthreads();
        #pragma unroll
        for (int r = 0; r < 2; r++) {
            int idx = tid + 256 * r;
            int row = idx >> 2, seg = (idx & 3) * 8;
            const float* src = Xr + (size_t)(m0 + row) * 128 + kc + seg;
            float4 fa = *(const float4*)src;
            float4 fb = *(const float4*)(src + 4);
            float vs[8] = {fa.x, fa.y, fa.z, fa.w, fb.x, fb.y, fb.z, fb.w};
            __align__(16) bf16 hs[8], ls[8];
            #pragma unroll
            for (int j = 0; j < 8; j++) {
                int ci = kc + seg + j;
                float y = vs[j] * ssc[ci] + ssh[ci];
                y = y >= 0.f ? y : 0.2f * y;
                bf16split(y, hs[j], ls[j]);
            }
            *(uint4*)(sAh + row * ALD + seg) = *(uint4*)hs;
            *(uint4*)(sAl + row * ALD + seg) = *(uint4*)ls;
        }
        #pragma unroll
        for (int r = 0; r < 2; r++) {
            int idx = tid + 256 * r;
            int row = idx >> 4, seg = (idx & 15) * 8;
            *(uint4*)(sBh + row * BLD + seg) =
                *(const uint4*)(Bhi + (size_t)(kc + row) * 4096 + n0 + seg);
            *(uint4*)(sBl + row * BLD + seg) =
                *(const uint4*)(Blo + (size_t)(kc + row) * 4096 + n0 + seg);
        }
        __syncthreads();
        #pragma unroll
        for (int k0 = 0; k0 < 32; k0 += 16) {
            wmma::fragment<wmma::matrix_a, 16, 16, 16, bf16, wmma::row_major> ah[2], al[2];
            #pragma unroll
            for (int i = 0; i < 2; i++) {
                wmma::load_matrix_sync(ah[i], sAh + (mw * 32 + i * 16) * ALD + k0, ALD);
                wmma::load_matrix_sync(al[i], sAl + (mw * 32 + i * 16) * ALD + k0, ALD);
            }
            #pragma unroll
            for (int j = 0; j < 4; j++) {
                wmma::fragment<wmma::matrix_b, 16, 16, 16, bf16, wmma::row_major> bh, bl;
                wmma::load_matrix_sync(bh, sBh + k0 * BLD + nw * 64 + j * 16, BLD);
                wmma::load_matrix_sync(bl, sBl + k0 * BLD + nw * 64 + j * 16, BLD);
                #pragma unroll
                for (int i = 0; i < 2; i++) {
                    wmma::mma_sync(c[i][j], ah[i], bh, c[i][j]);
                    wmma::mma_sync(c[i][j], ah[i], bl, c[i][j]);
                    wmma::mma_sync(c[i][j], al[i], bh, c[i][j]);
                }
            }
        }
    }
    __syncthreads();
    #pragma unroll
    for (int i = 0; i < 2; i++)
        #pragma unroll
        for (int j = 0; j < 4; j++)
            wmma::store_matrix_sync(Zt + (mw * 32 + i * 16) * ZLD + nw * 64 + j * 16,
                                    c[i][j], ZLD, wmma::mem_row_major);
    __syncthreads();

    // fold epilogue -> g_y2t[(b*32+t)][co]
    const float* Bi = s_ ? wB2 : hB2;
    int pair = tid >> 2, sub = tid & 3;
    int bb = pair >> 3, cc = pair & 7;
    int b  = blockIdx.y * 8 + bb;
    int co = blockIdx.x * 8 + cc;
    float bias = Bi[co];
    float psum = 0.f, psq = 0.f;
    float* yo = g_y2t[s_] + (size_t)b * 32 * 256 + co;
    const float* zrow = Zt + (bb * 16) * ZLD + cc * 16;
    #pragma unroll
    for (int ti = 0; ti < 8; ti++) {
        int t = sub + ti * 4;
        float v = 0.f;
        if (t < 31) {
            #pragma unroll
            for (int k = 0; k < 16; k++) {
                int s2 = t - k;
                if (s2 >= 0 && s2 < 16) v += zrow[s2 * ZLD + k];
            }
            v += bias;
        }
        yo[t * 256] = v;
        psum += v;
        psq  += v * v;
    }
    psum += __shfl_down_sync(0xffffffffu, psum, 2, 4);
    psum += __shfl_down_sync(0xffffffffu, psum, 1, 4);
    psq  += __shfl_down_sync(0xffffffffu, psq, 2, 4);
    psq  += __shfl_down_sync(0xffffffffu, psq, 1, 4);
    if (sub == 0) {
        g_psum[s_ * 65536 + b * 256 + co] = psum;
        g_psq [s_ * 65536 + b * 256 + co] = psq;
    }
}

// ---------------------------------------------------------------------------
// Stage 3b: BN2 partial reduce. grid 16 x 256.
// ---------------------------------------------------------------------------
__global__ void __launch_bounds__(256)
k_bnstat(const float* __restrict__ hG, const float* __restrict__ hBe,
         const float* __restrict__ wG, const float* __restrict__ wBe) {
    int s_  = blockIdx.x >> 3;
    int co0 = (blockIdx.x & 7) * 32;
    int col = threadIdx.x & 31, bp = threadIdx.x >> 5;
    const float* ps = g_psum + s_ * 65536 + co0 + col;
    const float* pq = g_psq  + s_ * 65536 + co0 + col;
    float sum = 0.f, sq = 0.f;
    #pragma unroll 8
    for (int i = 0; i < 32; i++) {
        int b = bp + 8 * i;
        sum += ps[b * 256];
        sq  += pq[b * 256];
    }
    __shared__ float ssum[8][32], ssq[8][32];
    ssum[bp][col] = sum; ssq[bp][col] = sq;
    __syncthreads();
    if (bp == 0) {
        #pragma unroll
        for (int r = 1; r < 8; r++) { sum += ssum[r][col]; sq += ssq[r][col]; }
        const float* G  = s_ ? wG  : hG;
        const float* Be = s_ ? wBe : hBe;
        int co = co0 + col;
        const float invN = 1.f / (256.f * 31.f);
        float mean = sum * invN, var = sq * invN - mean * mean;
        float sc = G[co] * rsqrtf(var + 1e-5f);
        g_sc[s_ * 256 + co] = sc;
        g_sh[s_ * 256 + co] = Be[co] - mean * sc;
    }
}

// ---------------------------------------------------------------------------
// Stage 4: convT2 GEMM, BN2+lrelu+split fused into A loader (t==31 rows zero);
// epilogue folds k=2 + tanh + coalesced store. grid (8,64,2), 256 threads.
// ---------------------------------------------------------------------------
__global__ void __launch_bounds__(256)
k_gemm2(const float* __restrict__ hB3, const float* __restrict__ wB3) {
    extern __shared__ char smraw[];
    float* Zt = (float*)smraw;
    bf16* sAh = (bf16*)smraw;
    bf16* sAl = sAh + A_ELEMS;
    bf16* sBh = sAl + A_ELEMS;
    bf16* sBl = sBh + B_ELEMS;
    __shared__ float ssc[256], ssh[256];
    int s_ = blockIdx.z;
    int m0 = blockIdx.y * 128, n0 = blockIdx.x * 128;
    int tid = threadIdx.x, w = tid >> 5, mw = w >> 1, nw = w & 1;
    ssc[tid] = g_sc[s_ * 256 + tid];
    ssh[tid] = g_sh[s_ * 256 + tid];
    const bf16* Bhi = g_w3hi[s_];
    const bf16* Blo = g_w3lo[s_];
    const float* Xr = g_y2t[s_];

    wmma::fragment<wmma::accumulator, 16, 16, 16, float> c[2][4];
    #pragma unroll
    for (int i = 0; i < 2; i++)
        #pragma unroll
        for (int j = 0; j < 4; j++) wmma::fill_fragment(c[i][j], 0.f);

    for (int kc = 0; kc < 256; kc += 32) {
        __syncthreads();
        #pragma unroll
        for (int r = 0; r < 2; r++) {
            int idx = tid + 256 * r;
            int row = idx >> 2, seg = (idx & 3) * 8;
            const float* src = Xr + (size_t)(m0 + row) * 256 + kc + seg;
            float4 fa = *(const float4*)src;
            float4 fb = *(const float4*)(src + 4);
            float vs[8] = {fa.x, fa.y, fa.z, fa.w, fb.x, fb.y, fb.z, fb.w};
            bool zero = (row & 31) == 31;              // t==31 rows are zero input
            __align__(16) bf16 hs[8], ls[8];
            #pragma unroll
            for (int j = 0; j < 8; j++) {
                int ci = kc + seg + j;
                float y = vs[j] * ssc[ci] + ssh[ci];
                y = y >= 0.f ? y : 0.2f * y;
                if (zero) y = 0.f;
                bf16split(y, hs[j], ls[j]);
            }
            *(uint4*)(sAh + row * ALD + seg) = *(uint4*)hs;
            *(uint4*)(sAl + row * ALD + seg) = *(uint4*)ls;
        }
        #pragma unroll
        for (int r = 0; r < 2; r++) {
            int idx = tid + 256 * r;
            int row = idx >> 4, seg = (idx & 15) * 8;
            *(uint4*)(sBh + row * BLD + seg) =
                *(const uint4*)(Bhi + (size_t)(kc + row) * 1024 + n0 + seg);
            *(uint4*)(sBl + row * BLD + seg) =
                *(const uint4*)(Blo + (size_t)(kc + row) * 1024 + n0 + seg);
        }
        __syncthreads();
        #pragma unroll
        for (int k0 = 0; k0 < 32; k0 += 16) {
            wmma::fragment<wmma::matrix_a, 16, 16, 16, bf16, wmma::row_major> ah[2], al[2];
            #pragma unroll
            for (int i = 0; i < 2; i++) {
                wmma::load_matrix_sync(ah[i], sAh + (mw * 32 + i * 16) * ALD + k0, ALD);
                wmma::load_matrix_sync(al[i], sAl + (mw * 32 + i * 16) * ALD + k0, ALD);
            }
            #pragma unroll
            for (int j = 0; j < 4; j++) {
                wmma::fragment<wmma::matrix_b, 16, 16, 16, bf16, wmma::row_major> bh, bl;
                wmma::load_matrix_sync(bh, sBh + k0 * BLD + nw * 64 + j * 16, BLD);
                wmma::load_matrix_sync(bl, sBl + k0 * BLD + nw * 64 + j * 16, BLD);
                #pragma unroll
                for (int i = 0; i < 2; i++) {
                    wmma::mma_sync(c[i][j], ah[i], bh, c[i][j]);
                    wmma::mma_sync(c[i][j], ah[i], bl, c[i][j]);
                    wmma::mma_sync(c[i][j], al[i], bh, c[i][j]);
                }
            }
        }
    }
    __syncthreads();
    #pragma unroll
    for (int i = 0; i < 2; i++)
        #pragma unroll
        for (int j = 0; j < 4; j++)
            wmma::store_matrix_sync(Zt + (mw * 32 + i * 16) * ZLD + nw * 64 + j * 16,
                                    c[i][j], ZLD, wmma::mem_row_major);
    __syncthreads();

    const float* Bi = s_ ? wB3 : hB3;
    int bb = tid >> 6, co = tid & 63;
    float bias = Bi[blockIdx.x * 64 + co];
    float y[32];
    const float* zb = Zt + (bb * 32) * ZLD;
    #pragma unroll
    for (int t = 0; t < 32; t++) {
        float z = zb[t * ZLD + co * 2] + bias;
        if (t > 0) z += zb[(t - 1) * ZLD + co * 2 + 1];
        y[t] = tanhf(z);
    }
    __syncthreads();
    float* yb = Zt + 128 * ZLD;
    #pragma unroll
    for (int t = 0; t < 32; t++) yb[(bb * 64 + co) * 36 + t] = y[t];
    __syncthreads();
    #pragma unroll
    for (int b2 = 0; b2 < 4; b2++) {
        float* o = g_o3 + s_ * (256 * 512 * 32)
                 + (((blockIdx.y * 4 + b2) * 512) + blockIdx.x * 64) * 32;
        for (int i = tid; i < 2048; i += 256)
            o[i] = yb[(b2 * 64 + (i >> 5)) * 36 + (i & 31)];
    }
}

// ---------------------------------------------------------------------------
// Stage 5: out[b,ch,y,x] = sum_r lrelu(BN(craw))*coef * h * w.
// grid 512 (b x y-half), 512 threads.
// ---------------------------------------------------------------------------
__global__ void __launch_bounds__(512)
k_final(const float* __restrict__ coef, float* __restrict__ out) {
    int b = blockIdx.x >> 1, yh = (blockIdx.x & 1) * 16;
    int tid = threadIdx.x;
    int y = yh + (tid >> 5), x = tid & 31;
    __shared__ float shh[32 * 32], shw[32 * 32], shc[96];
    float a0 = 0.f, a1 = 0.f, a2 = 0.f;
    int ri = tid >> 5, rp = tid & 31;
    for (int r0 = 0; r0 < 512; r0 += 32) {
        shh[tid]       = g_o3[                 (b * 512 + r0 + ri) * 32 + rp];
        shh[tid + 512] = g_o3[                 (b * 512 + r0 + 16 + ri) * 32 + rp];
        shw[tid]       = g_o3[256 * 512 * 32 + (b * 512 + r0 + ri) * 32 + rp];
        shw[tid + 512] = g_o3[256 * 512 * 32 + (b * 512 + r0 + 16 + ri) * 32 + rp];
        if (tid < 96) {
            int rr = tid / 3, c3 = tid % 3;
            int co = r0 + rr;
            float v = g_craw[b * 1536 + co * 3 + c3] * g_sc1c[co] + g_sh1c[co];
            v = v >= 0.f ? v : 0.2f * v;
            shc[tid] = v * coef[co];
        }
        __syncthreads();
        #pragma unroll
        for (int i = 0; i < 32; i++) {
            float p = shh[i * 32 + y] * shw[i * 32 + x];
            a0 += shc[i * 3 + 0] * p;
            a1 += shc[i * 3 + 1] * p;
            a2 += shc[i * 3 + 2] * p;
        }
        __syncthreads();
    }
    out[((b * 3 + 0) * 32 + y) * 32 + x] = a0;
    out[((b * 3 + 1) * 32 + y) * 32 + x] = a1;
    out[((b * 3 + 2) * 32 + y) * 32 + x] = a2;
}

// ---------------------------------------------------------------------------
extern "C" void kernel_launch(void* const* d_in, const int* in_sizes, int n_in,
                              void* d_out, int out_size) {
    const float* noise  = (const float*)d_in[0];
    const int*   label  = (const int*)  d_in[1];
    const float* lin_w  = (const float*)d_in[2];
    const float* lin_b  = (const float*)d_in[3];
    const float* bn0_g  = (const float*)d_in[4];
    const float* bn0_b  = (const float*)d_in[5];
    const float* emb    = (const float*)d_in[6];
    const float* c_w1   = (const float*)d_in[7];
    const float* c_b1   = (const float*)d_in[8];
    const float* c_g1   = (const float*)d_in[9];
    const float* c_be1  = (const float*)d_in[10];
    const float* h_w1   = (const float*)d_in[11];
    const float* h_b1   = (const float*)d_in[12];
    const float* h_g1   = (const float*)d_in[13];
    const float* h_be1  = (const float*)d_in[14];
    const float* h_w2   = (const float*)d_in[15];
    const float* h_b2   = (const float*)d_in[16];
    const float* h_g2   = (const float*)d_in[17];
    const float* h_be2  = (const float*)d_in[18];
    const float* h_w3   = (const float*)d_in[19];
    const float* h_b3   = (const float*)d_in[20];
    const float* w_w1   = (const float*)d_in[21];
    const float* w_b1   = (const float*)d_in[22];
    const float* w_g1   = (const float*)d_in[23];
    const float* w_be1  = (const float*)d_in[24];
    const float* w_w2   = (const float*)d_in[25];
    const float* w_b2   = (const float*)d_in[26];
    const float* w_g2   = (const float*)d_in[27];
    const float* w_be2  = (const float*)d_in[28];
    const float* w_w3   = (const float*)d_in[29];
    const float* w_b3   = (const float*)d_in[30];
    const float* coef   = (const float*)d_in[31];
    float* out = (float*)d_out;

    cudaFuncSetAttribute(k_gemm1,  cudaFuncAttributeMaxDynamicSharedMemorySize, SM_G16_B);
    cudaFuncSetAttribute(k_gemm16, cudaFuncAttributeMaxDynamicSharedMemorySize, SM_G16_B);
    cudaFuncSetAttribute(k_gemm2,  cudaFuncAttributeMaxDynamicSharedMemorySize, SM_G2_B);

    k_wprep  <<<11798, 256>>>(c_w1, h_w1, w_w1, c_b1, h_b1, w_b1,
                              h_w2, w_w2, h_w3, w_w3);
    k_latent <<<256,  256>>>(noise, label, lin_w, lin_b, bn0_g, bn0_b, emb);
    k_gemm1  <<<dim3(44, 2), 256, SM_G16_B>>>();
    k_bnstat1<<<3,    256>>>(c_g1, c_be1, h_g1, h_be1, w_g1, w_be1);
    k_gemm16 <<<dim3(32, 32, 2), 256, SM_G16_B>>>(h_b2, w_b2);
    k_bnstat <<<16,   256>>>(h_g2, h_be2, w_g2, w_be2);
    k_gemm2  <<<dim3(8, 64, 2), 256, SM_G2_B>>>(h_b3, w_b3);
    k_final  <<<512,  512>>>(coef, out);
}